// round 14
// baseline (speedup 1.0000x reference)
#include <cuda_runtime.h>
#include <cstdint>
#include <math.h>

#define NTOK 2048
#define HD   2048
#define ID   7168
#define NE   8
#define NR   64
#define EC   (NE*NR)       // 512
#define KDOWN (ID+EC)      // 7680
#define NF   (2*ID+2*EC)   // 15360
#define SCALE 0.25f
#define NSLOT (2*NTOK)     // 4096
#define MAXTILE 40

// main GEMM tiling: 256x128x32, 3 stages, 256 threads (8 warps, 4x2 of 64x64)
#define BM 256
#define BN 128
#define STAGES 3
#define STAGE_FLOATS 12288          // A 8192 + B 4096
#define STAGE_BYTES  49152
#define SMEM_BYTES   (STAGES*STAGE_BYTES)   // 147456

// gateup v2: 4 matrices x (2 chunks x 128 x 32 floats) = 128KB
#define GU_MATF 8192
#define GU_SMEM_BYTES (4*GU_MATF*4)

// corr kernel: 128x64x32, 3 stages
#define CK 1792
#define C_STAGE_FLOATS 6144
#define C_STAGE_BYTES 24576
#define C_SMEM_BYTES (3*C_STAGE_BYTES)

// ---------------- scratch ----------------
__device__ float g_xc     [(size_t)NTOK*HD];
__device__ float g_fusedW [(size_t)NF*HD];
__device__ float g_baseout[(size_t)NTOK*NF];
__device__ float g_hs     [(size_t)NSLOT*ID];
__device__ float g_hmixext[(size_t)NTOK*KDOWN];
__device__ float g_corrp  [(size_t)4*NSLOT*NR];
__device__ float g_bcomb  [(size_t)HD*KDOWN];
__device__ float g_dac    [(size_t)EC*ID];
__device__ float g_gBc    [(size_t)NE*ID*NR];
__device__ float g_uBc    [(size_t)NE*ID*NR];
__device__ int   g_eids   [NSLOT];
__device__ float g_wts    [NSLOT];
__device__ int   g_cnt    [NE];
__device__ int   g_list   [NE*NSLOT];
__device__ int   g_tile_e [MAXTILE+8];
__device__ int   g_tile_base[MAXTILE+8];
__device__ int   g_ntiles;

// ---------------- helpers ----------------
__device__ __forceinline__ float f2tf32f(float x){
    uint32_t r;
    asm("cvt.rna.tf32.f32 %0, %1;" : "=r"(r) : "f"(x));
    return __uint_as_float(r);
}
__device__ __forceinline__ void mma_tf32(float* c, const uint32_t* a, const uint32_t* b){
    asm volatile(
        "mma.sync.aligned.m16n8k8.row.col.f32.tf32.tf32.f32 "
        "{%0,%1,%2,%3}, {%4,%5,%6,%7}, {%8,%9}, {%0,%1,%2,%3};"
        : "+f"(c[0]), "+f"(c[1]), "+f"(c[2]), "+f"(c[3])
        : "r"(a[0]), "r"(a[1]), "r"(a[2]), "r"(a[3]), "r"(b[0]), "r"(b[1]));
}
__device__ __forceinline__ void cp16(uint32_t smaddr, const void* g){
    asm volatile("cp.async.cg.shared.global [%0], [%1], 16;" :: "r"(smaddr), "l"(g));
}
__device__ __forceinline__ void cp16z(uint32_t smaddr, const void* g, uint32_t bytes){
    asm volatile("cp.async.cg.shared.global [%0], [%1], 16, %2;"
                 :: "r"(smaddr), "l"(g), "r"(bytes));
}
__device__ __forceinline__ void cp_commit(){
    asm volatile("cp.async.commit_group;" ::: "memory");
}
template<int N> __device__ __forceinline__ void cp_wait(){
    asm volatile("cp.async.wait_group %0;" :: "n"(N) : "memory");
}

// ---------------- main tf32 GEMM: C[M,N] = A[M,K]*B[N,K]^T ----------------
// 256 threads: 8 warps in 4x2, each computing a 64x64 tile.
// Requires M%256==0, N%128==0, K%32==0.
__global__ __launch_bounds__(256, 1) void gemm_tf32(
        const float* __restrict__ A, const float* __restrict__ B,
        float* __restrict__ C, int M, int N, int K, int lda, int ldb, int roundN){
    extern __shared__ float sm[];
    const int tid = threadIdx.x;
    const int wid = tid >> 5, lane = tid & 31;
    const int wm = wid >> 1, wn = wid & 1;      // 4x2 warps, 64x64 tiles
    const int grp = lane >> 2, tig = lane & 3;
    const int m0 = blockIdx.y * BM, n0 = blockIdx.x * BN;
    uint32_t smem_base = (uint32_t)__cvta_generic_to_shared(sm);

    // cp.async mapping: 256 threads; A 8x16B, B 4x16B per thread per chunk
    const int rA = tid >> 3;             // 0..31
    const int cc = (tid & 7) << 2;
    const uint32_t ccs = (uint32_t)cc ^ (((uint32_t)(rA & 7)) << 2);
    const float* Agp = A + (size_t)(m0 + rA) * lda + cc;
    const float* Bgp = B + (size_t)(n0 + rA) * ldb + cc;
    const size_t rstepA = (size_t)32 * lda;
    const size_t rstepB = (size_t)32 * ldb;

    uint32_t dstA[8], dstB[4];
    #pragma unroll
    for (int q = 0; q < 8; q++) dstA[q] = ((uint32_t)(rA + 32*q) * 32u + ccs) * 4u;
    #pragma unroll
    for (int q = 0; q < 4; q++) dstB[q] = 32768u + ((uint32_t)(rA + 32*q) * 32u + ccs) * 4u;

    const int nch = K >> 5;

    #pragma unroll
    for (int s = 0; s < STAGES-1; s++){
        if (s < nch){
            uint32_t base = smem_base + (uint32_t)s * STAGE_BYTES;
            const float* ag = Agp + (s << 5);
            const float* bg = Bgp + (s << 5);
            #pragma unroll
            for (int q = 0; q < 8; q++) cp16(base + dstA[q], ag + rstepA * q);
            #pragma unroll
            for (int q = 0; q < 4; q++) cp16(base + dstB[q], bg + rstepB * q);
        }
        cp_commit();
    }

    const uint32_t gx = (uint32_t)grp << 2;
    uint32_t aRow[4], bRow[8];
    #pragma unroll
    for (int i = 0; i < 4; i++) aRow[i] = (uint32_t)(wm*64 + i*16 + grp) * 32u;
    #pragma unroll
    for (int j = 0; j < 8; j++) bRow[j] = 8192u + (uint32_t)(wn*64 + j*8 + grp) * 32u;

    float acc[4][8][4];
    #pragma unroll
    for (int i = 0; i < 4; i++)
        #pragma unroll
        for (int j = 0; j < 8; j++)
            #pragma unroll
            for (int q = 0; q < 4; q++) acc[i][j][q] = 0.f;

    for (int c = 0; c < nch; c++){
        cp_wait<STAGES-2>();
        __syncthreads();
        if (c + STAGES-1 < nch){
            const int cn = c + STAGES-1;
            uint32_t base = smem_base + (uint32_t)(cn % STAGES) * STAGE_BYTES;
            const float* ag = Agp + (cn << 5);
            const float* bg = Bgp + (cn << 5);
            #pragma unroll
            for (int q = 0; q < 8; q++) cp16(base + dstA[q], ag + rstepA * q);
            #pragma unroll
            for (int q = 0; q < 4; q++) cp16(base + dstB[q], bg + rstepB * q);
        }
        cp_commit();

        const uint32_t* st = (const uint32_t*)(sm + (size_t)(c % STAGES) * STAGE_FLOATS);
        #pragma unroll
        for (int kk = 0; kk < 4; kk++){
            const uint32_t k0 = ((uint32_t)(kk*8) + tig) ^ gx;
            const uint32_t k1 = ((uint32_t)(kk*8) + tig + 4u) ^ gx;
            uint32_t af[4][4], bf[8][2];
            #pragma unroll
            for (int i = 0; i < 4; i++){
                af[i][0] = st[aRow[i] + k0];
                af[i][1] = st[aRow[i] + 256u + k0];
                af[i][2] = st[aRow[i] + k1];
                af[i][3] = st[aRow[i] + 256u + k1];
            }
            #pragma unroll
            for (int j = 0; j < 8; j++){
                bf[j][0] = st[bRow[j] + k0];
                bf[j][1] = st[bRow[j] + k1];
            }
            #pragma unroll
            for (int i = 0; i < 4; i++)
                #pragma unroll
                for (int j = 0; j < 8; j++)
                    mma_tf32(acc[i][j], af[i], bf[j]);
        }
    }

    #pragma unroll
    for (int i = 0; i < 4; i++){
        int r0 = m0 + wm*64 + i*16 + grp;
        float* cr0 = C + (size_t)r0 * N;
        float* cr1 = C + (size_t)(r0 + 8) * N;
        #pragma unroll
        for (int j = 0; j < 8; j++){
            int col = n0 + wn*64 + j*8 + (tig << 1);
            float v0 = acc[i][j][0], v1 = acc[i][j][1];
            float v2 = acc[i][j][2], v3 = acc[i][j][3];
            if (col >= roundN){
                v0 = f2tf32f(v0); v1 = f2tf32f(v1);
                v2 = f2tf32f(v2); v3 = f2tf32f(v3);
            }
            *(float2*)(cr0 + col) = make_float2(v0, v1);
            *(float2*)(cr1 + col) = make_float2(v2, v3);
        }
    }
}

// ---------------- conv ----------------
__global__ void conv_kernel(const float* __restrict__ in, float* __restrict__ out){
    size_t i4 = ((size_t)blockIdx.x * 256 + threadIdx.x) << 2;
    float4 v = *(const float4*)(in + i4);
    v.x = f2tf32f(v.x); v.y = f2tf32f(v.y); v.z = f2tf32f(v.z); v.w = f2tf32f(v.w);
    *(float4*)(out + i4) = v;
}

// ---------------- routing + scatter ----------------
__global__ void zero_cnt_kernel(){ if (threadIdx.x < NE) g_cnt[threadIdx.x] = 0; }

__global__ void routing_kernel(const float* __restrict__ x,
                               const float* __restrict__ cw,
                               const float* __restrict__ cb,
                               const float* __restrict__ wealth){
    int t = blockIdx.x;
    int w = threadIdx.x >> 5, lane = threadIdx.x & 31;
    const float* xr = x + (size_t)t * HD;
    const float* cr = cw + (size_t)w * HD;
    float s = 0.f;
    for (int j = lane; j < HD; j += 32) s += xr[j] * cr[j];
    #pragma unroll
    for (int o = 16; o; o >>= 1) s += __shfl_down_sync(0xffffffffu, s, o);
    __shared__ float bids[NE];
    if (lane == 0){
        float conf = 1.f / (1.f + expf(-(s + cb[w])));
        bids[w] = conf * wealth[w];
    }
    __syncthreads();
    if (threadIdx.x == 0){
        int e0 = 0; float b0 = bids[0];
        for (int e = 1; e < NE; e++) if (bids[e] > b0){ b0 = bids[e]; e0 = e; }
        int e1 = -1; float b1 = -1e30f;
        for (int e = 0; e < NE; e++) if (e != e0 && bids[e] > b1){ b1 = bids[e]; e1 = e; }
        float ed = expf(b1 - b0);
        float inv = 1.f / (1.f + ed);
        g_eids[2*t] = e0; g_eids[2*t+1] = e1;
        g_wts [2*t] = inv; g_wts [2*t+1] = ed * inv;
        int p0 = atomicAdd(&g_cnt[e0], 1); g_list[e0*NSLOT + p0] = 2*t;
        int p1 = atomicAdd(&g_cnt[e1], 1); g_list[e1*NSLOT + p1] = 2*t + 1;
    }
}

__global__ void tilemeta_kernel(){
    if (threadIdx.x == 0){
        int nt = 0;
        for (int e = 0; e < NE; e++){
            int c = g_cnt[e];
            for (int b = 0; b < c; b += 128){
                g_tile_e[nt] = e; g_tile_base[nt] = b; nt++;
            }
        }
        g_ntiles = nt;
    }
}

// ---------------- gateup v2 ----------------
__global__ __launch_bounds__(256, 1) void gateup_kernel(){
    int tileid = blockIdx.y;
    if (tileid >= g_ntiles) return;
    const int e = g_tile_e[tileid];
    const int tbase = g_tile_base[tileid];
    const int cnt = g_cnt[e];
    const int i0 = blockIdx.x << 7;
    extern __shared__ float sm[];
    __shared__ int s_ent[128];
    const int tid = threadIdx.x;
    if (tid < 128){
        int j = tbase + tid;
        s_ent[tid] = (j < cnt) ? g_list[e*NSLOT + j] : -1;
    }
    __syncthreads();
    uint32_t smem_base = (uint32_t)__cvta_generic_to_shared(sm);

    {
        const int rA = tid >> 3;
        const int cc = (tid & 7) << 2;
        const uint32_t ccs = (uint32_t)cc ^ (((uint32_t)(rA & 7)) << 2);
        #pragma unroll
        for (int q = 0; q < 4; q++){
            const int row = rA + 32*q;
            const int ent = s_ent[row];
            const int t = ent >> 1;
            const uint32_t abytes = (ent >= 0) ? 16u : 0u;
            const float* asrc = (ent >= 0)
                ? (g_baseout + (size_t)t*NF + 2*ID + e*NR)
                : g_baseout;
            const float* bsrcg = g_gBc + ((size_t)e*ID + i0 + row)*NR;
            const float* bsrcu = g_uBc + ((size_t)e*ID + i0 + row)*NR;
            #pragma unroll
            for (int ch = 0; ch < 2; ch++){
                const uint32_t dst = ((uint32_t)ch*4096u + (uint32_t)row*32u + ccs)*4u;
                const int kof = ch*32 + cc;
                cp16z(smem_base + dst,                 asrc + kof,      abytes);
                cp16z(smem_base + 32768u + dst,        asrc + EC + kof, abytes);
                cp16 (smem_base + 65536u + dst,        bsrcg + kof);
                cp16 (smem_base + 98304u + dst,        bsrcu + kof);
            }
        }
        cp_commit();
    }
    cp_wait<0>();
    __syncthreads();

    const int wid = tid >> 5, lane = tid & 31;
    const int wm = wid >> 2, wn = wid & 3;
    const int grp = lane >> 2, tig = lane & 3;
    const uint32_t gx = (uint32_t)grp << 2;
    const uint32_t* uAg = (const uint32_t*)sm;
    const uint32_t* uAu = (const uint32_t*)(sm + GU_MATF);
    const uint32_t* uBg = (const uint32_t*)(sm + 2*GU_MATF);
    const uint32_t* uBu = (const uint32_t*)(sm + 3*GU_MATF);

    uint32_t aRow[4], bRow[4];
    #pragma unroll
    for (int i = 0; i < 4; i++) aRow[i] = (uint32_t)(wm*64 + i*16 + grp) * 32u;
    #pragma unroll
    for (int j = 0; j < 4; j++) bRow[j] = (uint32_t)(wn*32 + j*8 + grp) * 32u;

    float accg[4][4][4], accu[4][4][4];
    #pragma unroll
    for (int i = 0; i < 4; i++)
        #pragma unroll
        for (int j = 0; j < 4; j++)
            #pragma unroll
            for (int q = 0; q < 4; q++){ accg[i][j][q]=0.f; accu[i][j][q]=0.f; }

    #pragma unroll
    for (int ch = 0; ch < 2; ch++){
        const uint32_t cb = (uint32_t)ch * 4096u;
        #pragma unroll
        for (int kk = 0; kk < 4; kk++){
            const uint32_t k0 = ((uint32_t)(kk*8) + tig) ^ gx;
            const uint32_t k1 = ((uint32_t)(kk*8) + tig + 4u) ^ gx;
            uint32_t ag[4][4], au[4][4], bg[4][2], bu[4][2];
            #pragma unroll
            for (int i = 0; i < 4; i++){
                ag[i][0] = uAg[cb + aRow[i] + k0];
                ag[i][1] = uAg[cb + aRow[i] + 256u + k0];
                ag[i][2] = uAg[cb + aRow[i] + k1];
                ag[i][3] = uAg[cb + aRow[i] + 256u + k1];
                au[i][0] = uAu[cb + aRow[i] + k0];
                au[i][1] = uAu[cb + aRow[i] + 256u + k0];
                au[i][2] = uAu[cb + aRow[i] + k1];
                au[i][3] = uAu[cb + aRow[i] + 256u + k1];
            }
            #pragma unroll
            for (int j = 0; j < 4; j++){
                bg[j][0] = uBg[cb + bRow[j] + k0];
                bg[j][1] = uBg[cb + bRow[j] + k1];
                bu[j][0] = uBu[cb + bRow[j] + k0];
                bu[j][1] = uBu[cb + bRow[j] + k1];
            }
            #pragma unroll
            for (int i = 0; i < 4; i++)
                #pragma unroll
                for (int j = 0; j < 4; j++){
                    mma_tf32(accg[i][j], ag[i], bg[j]);
                    mma_tf32(accu[i][j], au[i], bu[j]);
                }
        }
    }

    #pragma unroll
    for (int i = 0; i < 4; i++){
        #pragma unroll
        for (int half = 0; half < 2; half++){
            int r = wm*64 + i*16 + grp + half*8;
            int ent = s_ent[r];
            if (ent < 0) continue;
            int t = ent >> 1;
            float w = g_wts[ent];
            const float* brow = g_baseout + (size_t)t*NF;
            float* hrow = g_hs + (size_t)ent*ID;
            #pragma unroll
            for (int j = 0; j < 4; j++){
                int col = i0 + wn*32 + j*8 + (tig << 1);
                float2 bg2 = *(const float2*)(brow + col);
                float2 bu2 = *(const float2*)(brow + ID + col);
                float cg0 = accg[i][j][half*2+0], cg1 = accg[i][j][half*2+1];
                float cu0 = accu[i][j][half*2+0], cu1 = accu[i][j][half*2+1];
                float gate0 = bg2.x + SCALE*cg0, gate1 = bg2.y + SCALE*cg1;
                float up0 = bu2.x + SCALE*cu0,  up1 = bu2.y + SCALE*cu1;
                float h0 = gate0 * (1.f/(1.f+__expf(-gate0))) * up0;
                float h1 = gate1 * (1.f/(1.f+__expf(-gate1))) * up1;
                *(float2*)(hrow + col) = make_float2(f2tf32f(w*h0), f2tf32f(w*h1));
            }
        }
    }
}

// ---------------- grouped corr GEMM ----------------
__global__ __launch_bounds__(128, 2) void corr_kernel(){
    int tileid = blockIdx.y;
    if (tileid >= g_ntiles) return;
    const int e = g_tile_e[tileid];
    const int tbase = g_tile_base[tileid];
    const int cnt = g_cnt[e];
    const int ks = blockIdx.x;
    extern __shared__ float sm[];
    __shared__ int s_ent[128];
    const int tid = threadIdx.x;
    if (tid < 128){
        int j = tbase + tid;
        s_ent[tid] = (j < cnt) ? g_list[e*NSLOT + j] : -1;
    }
    __syncthreads();
    uint32_t smem_base = (uint32_t)__cvta_generic_to_shared(sm);

    const int rA = tid >> 3;
    const int cc = (tid & 7) << 2;
    const uint32_t ccs = (uint32_t)cc ^ (((uint32_t)(rA & 7)) << 2);
    const size_t koff0 = (size_t)ks*CK + cc;

    const float* Asrc[8]; uint32_t Abytes[8];
    #pragma unroll
    for (int q = 0; q < 8; q++){
        int ent = s_ent[rA + 16*q];
        Asrc[q] = (ent >= 0) ? (g_hs + (size_t)ent*ID + koff0) : g_hs;
        Abytes[q] = (ent >= 0) ? 16u : 0u;
    }
    const float* Bsrc[4];
    #pragma unroll
    for (int q = 0; q < 4; q++)
        Bsrc[q] = g_dac + (size_t)(e*NR + rA + 16*q)*ID + koff0;

    uint32_t dstA[8], dstB[4];
    #pragma unroll
    for (int q = 0; q < 8; q++) dstA[q] = ((uint32_t)(rA + 16*q) * 32u + ccs) * 4u;
    #pragma unroll
    for (int q = 0; q < 4; q++) dstB[q] = 16384u + ((uint32_t)(rA + 16*q) * 32u + ccs) * 4u;

    const int nch = CK >> 5;

    #pragma unroll
    for (int s = 0; s < 2; s++){
        uint32_t base = smem_base + (uint32_t)s * C_STAGE_BYTES;
        #pragma unroll
        for (int q = 0; q < 8; q++) cp16z(base + dstA[q], Asrc[q] + (s<<5), Abytes[q]);
        #pragma unroll
        for (int q = 0; q < 4; q++) cp16(base + dstB[q], Bsrc[q] + (s<<5));
        cp_commit();
    }

    const int wid = tid >> 5, lane = tid & 31;
    const int wm = wid >> 1, wn = wid & 1;
    const int grp = lane >> 2, tig = lane & 3;
    const uint32_t gx = (uint32_t)grp << 2;
    uint32_t aRow[4], bRow[4];
    #pragma unroll
    for (int i = 0; i < 4; i++) aRow[i] = (uint32_t)(wm*64 + i*16 + grp) * 32u;
    #pragma unroll
    for (int j = 0; j < 4; j++) bRow[j] = 4096u + (uint32_t)(wn*32 + j*8 + grp) * 32u;

    float acc[4][4][4];
    #pragma unroll
    for (int i = 0; i < 4; i++)
        #pragma unroll
        for (int j = 0; j < 4; j++)
            #pragma unroll
            for (int q = 0; q < 4; q++) acc[i][j][q] = 0.f;

    for (int c = 0; c < nch; c++){
        cp_wait<1>();
        __syncthreads();
        if (c + 2 < nch){
            const int cn = c + 2;
            uint32_t base = smem_base + (uint32_t)(cn % 3) * C_STAGE_BYTES;
            #pragma unroll
            for (int q = 0; q < 8; q++) cp16z(base + dstA[q], Asrc[q] + (cn<<5), Abytes[q]);
            #pragma unroll
            for (int q = 0; q < 4; q++) cp16(base + dstB[q], Bsrc[q] + (cn<<5));
        }
        cp_commit();

        const uint32_t* st = (const uint32_t*)(sm + (size_t)(c % 3) * C_STAGE_FLOATS);
        #pragma unroll
        for (int kk = 0; kk < 4; kk++){
            const uint32_t k0 = ((uint32_t)(kk*8) + tig) ^ gx;
            const uint32_t k1 = ((uint32_t)(kk*8) + tig + 4u) ^ gx;
            uint32_t af[4][4], bf[4][2];
            #pragma unroll
            for (int i = 0; i < 4; i++){
                af[i][0] = st[aRow[i] + k0];
                af[i][1] = st[aRow[i] + 256u + k0];
                af[i][2] = st[aRow[i] + k1];
                af[i][3] = st[aRow[i] + 256u + k1];
            }
            #pragma unroll
            for (int j = 0; j < 4; j++){
                bf[j][0] = st[bRow[j] + k0];
                bf[j][1] = st[bRow[j] + k1];
            }
            #pragma unroll
            for (int i = 0; i < 4; i++)
                #pragma unroll
                for (int j = 0; j < 4; j++)
                    mma_tf32(acc[i][j], af[i], bf[j]);
        }
    }

    #pragma unroll
    for (int i = 0; i < 4; i++){
        #pragma unroll
        for (int half = 0; half < 2; half++){
            int r = wm*64 + i*16 + grp + half*8;
            int ent = s_ent[r];
            if (ent < 0) continue;
            float* crow = g_corrp + ((size_t)ks*NSLOT + ent)*NR;
            #pragma unroll
            for (int j = 0; j < 4; j++){
                int col = wn*32 + j*8 + (tig << 1);
                *(float2*)(crow + col) =
                    make_float2(acc[i][j][half*2+0], acc[i][j][half*2+1]);
            }
        }
    }
}

// ---------------- bcomb ----------------
__global__ void bcomb_kernel(const float* __restrict__ bdw, const float* __restrict__ dB){
    size_t idx = (size_t)blockIdx.x * 256 + threadIdx.x;
    int h = (int)(idx / KDOWN); int k = (int)(idx % KDOWN);
    float v;
    if (k < ID) v = bdw[(size_t)h * ID + k];
    else { int j = k - ID; int e = j >> 6; int r = j & 63;
           v = dB[((size_t)e * HD + h) * NR + r]; }
    g_bcomb[idx] = f2tf32f(v);
}

// hmix head: hs0+hs1
__global__ void addhead_kernel(){
    size_t i4 = ((size_t)blockIdx.x * 256 + threadIdx.x) << 2;
    int t = (int)(i4 / ID); int col = (int)(i4 % ID);
    float4 a = *(const float4*)&g_hs[(size_t)(2*t)*ID + col];
    float4 b = *(const float4*)&g_hs[(size_t)(2*t+1)*ID + col];
    float4 o;
    o.x = f2tf32f(a.x+b.x); o.y = f2tf32f(a.y+b.y);
    o.z = f2tf32f(a.z+b.z); o.w = f2tf32f(a.w+b.w);
    *(float4*)&g_hmixext[(size_t)t * KDOWN + col] = o;
}

// cvec tail
__global__ void cvec_kernel(){
    int idx = blockIdx.x * 256 + threadIdx.x;
    int t = idx >> 9, j = idx & 511;
    int e = j >> 6, r = j & 63;
    float v = 0.f;
    #pragma unroll
    for (int k = 0; k < 2; k++){
        int ent = 2*t + k;
        if (g_eids[ent] == e){
            #pragma unroll
            for (int s = 0; s < 4; s++)
                v += g_corrp[((size_t)s*NSLOT + ent)*NR + r];
        }
    }
    g_hmixext[(size_t)t * KDOWN + ID + j] = f2tf32f(SCALE * v);
}

// ---------------- launch ----------------
static void launch_gemm_s(cudaStream_t st, const float* A, const float* B, float* C,
                          int M, int N, int K, int lda, int ldb, int roundN){
    dim3 grid(N / BN, M / BM);
    gemm_tf32<<<grid, 256, SMEM_BYTES, st>>>(A, B, C, M, N, K, lda, ldb, roundN);
}
static void launch_conv_s(cudaStream_t st, const float* in, float* out, size_t n){
    conv_kernel<<<(unsigned)((n / 4) / 256), 256, 0, st>>>(in, out);
}

extern "C" void kernel_launch(void* const* d_in, const int* in_sizes, int n_in,
                              void* d_out, int out_size){
    const float* x      = (const float*)d_in[0];
    const float* conf_w = (const float*)d_in[1];
    const float* conf_b = (const float*)d_in[2];
    const float* wealth = (const float*)d_in[3];
    const float* bgw    = (const float*)d_in[4];
    const float* buw    = (const float*)d_in[5];
    const float* bdw    = (const float*)d_in[6];
    const float* gA     = (const float*)d_in[7];
    const float* gB     = (const float*)d_in[8];
    const float* uA     = (const float*)d_in[9];
    const float* uB     = (const float*)d_in[10];
    const float* dA     = (const float*)d_in[11];
    const float* dB     = (const float*)d_in[12];
    float* out = (float*)d_out;

    static bool init_done = false;
    static cudaStream_t s1, s2;
    static cudaEvent_t evFork, evS1, evS2, evGate, evAdd;
    if (!init_done){
        cudaFuncSetAttribute(gemm_tf32, cudaFuncAttributeMaxDynamicSharedMemorySize, SMEM_BYTES);
        cudaFuncSetAttribute(gateup_kernel, cudaFuncAttributeMaxDynamicSharedMemorySize, GU_SMEM_BYTES);
        cudaFuncSetAttribute(corr_kernel, cudaFuncAttributeMaxDynamicSharedMemorySize, C_SMEM_BYTES);
        cudaStreamCreateWithFlags(&s1, cudaStreamNonBlocking);
        cudaStreamCreateWithFlags(&s2, cudaStreamNonBlocking);
        cudaEventCreateWithFlags(&evFork, cudaEventDisableTiming);
        cudaEventCreateWithFlags(&evS1,   cudaEventDisableTiming);
        cudaEventCreateWithFlags(&evS2,   cudaEventDisableTiming);
        cudaEventCreateWithFlags(&evGate, cudaEventDisableTiming);
        cudaEventCreateWithFlags(&evAdd,  cudaEventDisableTiming);
        init_done = true;
    }

    float *p_xc, *p_fusedW, *p_baseout, *p_hmixext, *p_dac, *p_bcomb, *p_gBc, *p_uBc;
    cudaGetSymbolAddress((void**)&p_xc,      g_xc);
    cudaGetSymbolAddress((void**)&p_fusedW,  g_fusedW);
    cudaGetSymbolAddress((void**)&p_baseout, g_baseout);
    cudaGetSymbolAddress((void**)&p_hmixext, g_hmixext);
    cudaGetSymbolAddress((void**)&p_dac,     g_dac);
    cudaGetSymbolAddress((void**)&p_bcomb,   g_bcomb);
    cudaGetSymbolAddress((void**)&p_gBc,     g_gBc);
    cudaGetSymbolAddress((void**)&p_uBc,     g_uBc);

    cudaStream_t s0 = 0;

    cudaEventRecord(evFork, s0);
    cudaStreamWaitEvent(s1, evFork, 0);
    cudaStreamWaitEvent(s2, evFork, 0);

    // s0: routing path + x conversion
    zero_cnt_kernel<<<1, 32, 0, s0>>>();
    routing_kernel<<<NTOK, 256, 0, s0>>>(x, conf_w, conf_b, wealth);
    tilemeta_kernel<<<1, 32, 0, s0>>>();
    launch_conv_s(s0, x, p_xc, (size_t)NTOK*HD);

    // s1: fusedW conversions
    launch_conv_s(s1, bgw, p_fusedW,                        (size_t)ID*HD);
    launch_conv_s(s1, buw, p_fusedW + (size_t)ID*HD,        (size_t)ID*HD);
    launch_conv_s(s1, gA,  p_fusedW + (size_t)2*ID*HD,      (size_t)EC*HD);
    launch_conv_s(s1, uA,  p_fusedW + (size_t)(2*ID+EC)*HD, (size_t)EC*HD);
    cudaEventRecord(evS1, s1);

    // s2: mid/down operand prep (hidden under x-GEMM)
    launch_conv_s(s2, gB, p_gBc, (size_t)NE*ID*NR);
    launch_conv_s(s2, uB, p_uBc, (size_t)NE*ID*NR);
    launch_conv_s(s2, dA, p_dac, (size_t)EC*ID);
    bcomb_kernel<<<((size_t)HD*KDOWN)/256, 256, 0, s2>>>(bdw, dB);
    cudaEventRecord(evS2, s2);

    // x-side fused GEMM
    cudaStreamWaitEvent(s0, evS1, 0);
    launch_gemm_s(s0, p_xc, p_fusedW, p_baseout, NTOK, NF, HD, HD, HD, 2*ID);

    // gateup v2
    cudaStreamWaitEvent(s0, evS2, 0);
    gateup_kernel<<<dim3(ID/128, MAXTILE), 256, GU_SMEM_BYTES, s0>>>();
    cudaEventRecord(evGate, s0);

    // addhead on s1 concurrent with corr on s0
    cudaStreamWaitEvent(s1, evGate, 0);
    addhead_kernel<<<(NTOK*ID/4)/256, 256, 0, s1>>>();
    cudaEventRecord(evAdd, s1);

    corr_kernel<<<dim3(4, MAXTILE), 128, C_SMEM_BYTES, s0>>>();
    cvec_kernel<<<(NTOK*EC)/256, 256, 0, s0>>>();

    // down projection joins addhead
    cudaStreamWaitEvent(s0, evAdd, 0);
    launch_gemm_s(s0, p_hmixext, p_bcomb, out, NTOK, HD, KDOWN, KDOWN, KDOWN, 1<<30);
}

// round 15
// speedup vs baseline: 1.0560x; 1.0560x over previous
#include <cuda_runtime.h>
#include <cstdint>
#include <math.h>

#define NTOK 2048
#define HD   2048
#define ID   7168
#define NE   8
#define NR   64
#define EC   (NE*NR)       // 512
#define KDOWN (ID+EC)      // 7680
#define NF   (2*ID+2*EC)   // 15360
#define SCALE 0.25f
#define NSLOT (2*NTOK)     // 4096
#define MAXTILE 40

// main GEMM tiling: 128x128x32, 3 stages, 128 threads (4 warps, 2x2 of 64x64)
#define BM 128
#define BN 128
#define STAGES 3
#define STAGE_FLOATS 8192
#define STAGE_BYTES  32768
#define SMEM_BYTES   (STAGES*STAGE_BYTES)

// gateup v2: 4 matrices x (2 chunks x 128 x 32 floats) = 128KB
#define GU_MATF 8192
#define GU_SMEM_BYTES (4*GU_MATF*4)

// corr kernel: 128x64x32, 3 stages
#define CK 1792
#define C_STAGE_FLOATS 6144
#define C_STAGE_BYTES 24576
#define C_SMEM_BYTES (3*C_STAGE_BYTES)

// ---------------- scratch ----------------
__device__ float g_xc     [(size_t)NTOK*HD];
__device__ float g_fusedW [(size_t)NF*HD];
__device__ float g_baseout[(size_t)NTOK*NF];
__device__ float g_hs     [(size_t)NSLOT*ID];
__device__ float g_hmixext[(size_t)NTOK*KDOWN];
__device__ float g_corrp  [(size_t)4*NSLOT*NR];
__device__ float g_bcomb  [(size_t)HD*KDOWN];
__device__ float g_dac    [(size_t)EC*ID];
__device__ float g_gBc    [(size_t)NE*ID*NR];
__device__ float g_uBc    [(size_t)NE*ID*NR];
__device__ int   g_eids   [NSLOT];
__device__ float g_wts    [NSLOT];
__device__ int   g_cnt    [NE];
__device__ int   g_list   [NE*NSLOT];
__device__ int   g_tile_e [MAXTILE+8];
__device__ int   g_tile_base[MAXTILE+8];
__device__ int   g_ntiles;

// ---------------- helpers ----------------
__device__ __forceinline__ float f2tf32f(float x){
    uint32_t r;
    asm("cvt.rna.tf32.f32 %0, %1;" : "=r"(r) : "f"(x));
    return __uint_as_float(r);
}
__device__ __forceinline__ void mma_tf32(float* c, const uint32_t* a, const uint32_t* b){
    asm volatile(
        "mma.sync.aligned.m16n8k8.row.col.f32.tf32.tf32.f32 "
        "{%0,%1,%2,%3}, {%4,%5,%6,%7}, {%8,%9}, {%0,%1,%2,%3};"
        : "+f"(c[0]), "+f"(c[1]), "+f"(c[2]), "+f"(c[3])
        : "r"(a[0]), "r"(a[1]), "r"(a[2]), "r"(a[3]), "r"(b[0]), "r"(b[1]));
}
__device__ __forceinline__ void cp16(uint32_t smaddr, const void* g){
    asm volatile("cp.async.cg.shared.global [%0], [%1], 16;" :: "r"(smaddr), "l"(g));
}
__device__ __forceinline__ void cp16z(uint32_t smaddr, const void* g, uint32_t bytes){
    asm volatile("cp.async.cg.shared.global [%0], [%1], 16, %2;"
                 :: "r"(smaddr), "l"(g), "r"(bytes));
}
__device__ __forceinline__ void cp_commit(){
    asm volatile("cp.async.commit_group;" ::: "memory");
}
template<int N> __device__ __forceinline__ void cp_wait(){
    asm volatile("cp.async.wait_group %0;" :: "n"(N) : "memory");
}

// ---------------- main tf32 GEMM: C[M,N] (+)= A[M,K]*B[N,K]^T ----------------
__global__ __launch_bounds__(128, 2) void gemm_tf32(
        const float* __restrict__ A, const float* __restrict__ B,
        float* __restrict__ C, int M, int N, int K, int lda, int ldb,
        int roundN, int accum){
    extern __shared__ float sm[];
    const int tid = threadIdx.x;
    const int wid = tid >> 5, lane = tid & 31;
    const int wm = wid >> 1, wn = wid & 1;
    const int grp = lane >> 2, tig = lane & 3;
    const int m0 = blockIdx.y * BM, n0 = blockIdx.x * BN;
    uint32_t smem_base = (uint32_t)__cvta_generic_to_shared(sm);

    const int rA = tid >> 3;
    const int cc = (tid & 7) << 2;
    const uint32_t ccs = (uint32_t)cc ^ (((uint32_t)(rA & 7)) << 2);
    const float* Agp = A + (size_t)(m0 + rA) * lda + cc;
    const float* Bgp = B + (size_t)(n0 + rA) * ldb + cc;
    const size_t rstepA = (size_t)16 * lda;
    const size_t rstepB = (size_t)16 * ldb;

    uint32_t dstA[8], dstB[8];
    #pragma unroll
    for (int q = 0; q < 8; q++){
        dstA[q] = ((uint32_t)(rA + 16*q) * 32u + ccs) * 4u;
        dstB[q] = 16384u + dstA[q];
    }
    const int nch = K >> 5;

    #pragma unroll
    for (int s = 0; s < STAGES-1; s++){
        if (s < nch){
            uint32_t base = smem_base + (uint32_t)s * STAGE_BYTES;
            const float* ag = Agp + (s << 5);
            const float* bg = Bgp + (s << 5);
            #pragma unroll
            for (int q = 0; q < 8; q++) cp16(base + dstA[q], ag + rstepA * q);
            #pragma unroll
            for (int q = 0; q < 8; q++) cp16(base + dstB[q], bg + rstepB * q);
        }
        cp_commit();
    }

    const uint32_t gx = (uint32_t)grp << 2;
    uint32_t aRow[4], bRow[8];
    #pragma unroll
    for (int i = 0; i < 4; i++) aRow[i] = (uint32_t)(wm*64 + i*16 + grp) * 32u;
    #pragma unroll
    for (int j = 0; j < 8; j++) bRow[j] = 4096u + (uint32_t)(wn*64 + j*8 + grp) * 32u;

    float acc[4][8][4];
    #pragma unroll
    for (int i = 0; i < 4; i++)
        #pragma unroll
        for (int j = 0; j < 8; j++)
            #pragma unroll
            for (int q = 0; q < 4; q++) acc[i][j][q] = 0.f;

    for (int c = 0; c < nch; c++){
        cp_wait<STAGES-2>();
        __syncthreads();
        if (c + STAGES-1 < nch){
            const int cn = c + STAGES-1;
            uint32_t base = smem_base + (uint32_t)(cn % STAGES) * STAGE_BYTES;
            const float* ag = Agp + (cn << 5);
            const float* bg = Bgp + (cn << 5);
            #pragma unroll
            for (int q = 0; q < 8; q++) cp16(base + dstA[q], ag + rstepA * q);
            #pragma unroll
            for (int q = 0; q < 8; q++) cp16(base + dstB[q], bg + rstepB * q);
        }
        cp_commit();

        const uint32_t* st = (const uint32_t*)(sm + (size_t)(c % STAGES) * STAGE_FLOATS);
        #pragma unroll
        for (int kk = 0; kk < 4; kk++){
            const uint32_t k0 = ((uint32_t)(kk*8) + tig) ^ gx;
            const uint32_t k1 = ((uint32_t)(kk*8) + tig + 4u) ^ gx;
            uint32_t af[4][4], bf[8][2];
            #pragma unroll
            for (int i = 0; i < 4; i++){
                af[i][0] = st[aRow[i] + k0];
                af[i][1] = st[aRow[i] + 256u + k0];
                af[i][2] = st[aRow[i] + k1];
                af[i][3] = st[aRow[i] + 256u + k1];
            }
            #pragma unroll
            for (int j = 0; j < 8; j++){
                bf[j][0] = st[bRow[j] + k0];
                bf[j][1] = st[bRow[j] + k1];
            }
            #pragma unroll
            for (int i = 0; i < 4; i++)
                #pragma unroll
                for (int j = 0; j < 8; j++)
                    mma_tf32(acc[i][j], af[i], bf[j]);
        }
    }

    #pragma unroll
    for (int i = 0; i < 4; i++){
        int r0 = m0 + wm*64 + i*16 + grp;
        float* cr0 = C + (size_t)r0 * N;
        float* cr1 = C + (size_t)(r0 + 8) * N;
        #pragma unroll
        for (int j = 0; j < 8; j++){
            int col = n0 + wn*64 + j*8 + (tig << 1);
            float v0 = acc[i][j][0], v1 = acc[i][j][1];
            float v2 = acc[i][j][2], v3 = acc[i][j][3];
            if (accum){
                float2 o0 = *(const float2*)(cr0 + col);
                float2 o1 = *(const float2*)(cr1 + col);
                v0 += o0.x; v1 += o0.y; v2 += o1.x; v3 += o1.y;
            }
            if (col >= roundN){
                v0 = f2tf32f(v0); v1 = f2tf32f(v1);
                v2 = f2tf32f(v2); v3 = f2tf32f(v3);
            }
            *(float2*)(cr0 + col) = make_float2(v0, v1);
            *(float2*)(cr1 + col) = make_float2(v2, v3);
        }
    }
}

// ---------------- conv ----------------
__global__ void conv_kernel(const float* __restrict__ in, float* __restrict__ out){
    size_t i4 = ((size_t)blockIdx.x * 256 + threadIdx.x) << 2;
    float4 v = *(const float4*)(in + i4);
    v.x = f2tf32f(v.x); v.y = f2tf32f(v.y); v.z = f2tf32f(v.z); v.w = f2tf32f(v.w);
    *(float4*)(out + i4) = v;
}

// ---------------- routing + scatter ----------------
__global__ void zero_cnt_kernel(){ if (threadIdx.x < NE) g_cnt[threadIdx.x] = 0; }

__global__ void routing_kernel(const float* __restrict__ x,
                               const float* __restrict__ cw,
                               const float* __restrict__ cb,
                               const float* __restrict__ wealth){
    int t = blockIdx.x;
    int w = threadIdx.x >> 5, lane = threadIdx.x & 31;
    const float* xr = x + (size_t)t * HD;
    const float* cr = cw + (size_t)w * HD;
    float s = 0.f;
    for (int j = lane; j < HD; j += 32) s += xr[j] * cr[j];
    #pragma unroll
    for (int o = 16; o; o >>= 1) s += __shfl_down_sync(0xffffffffu, s, o);
    __shared__ float bids[NE];
    if (lane == 0){
        float conf = 1.f / (1.f + expf(-(s + cb[w])));
        bids[w] = conf * wealth[w];
    }
    __syncthreads();
    if (threadIdx.x == 0){
        int e0 = 0; float b0 = bids[0];
        for (int e = 1; e < NE; e++) if (bids[e] > b0){ b0 = bids[e]; e0 = e; }
        int e1 = -1; float b1 = -1e30f;
        for (int e = 0; e < NE; e++) if (e != e0 && bids[e] > b1){ b1 = bids[e]; e1 = e; }
        float ed = expf(b1 - b0);
        float inv = 1.f / (1.f + ed);
        g_eids[2*t] = e0; g_eids[2*t+1] = e1;
        g_wts [2*t] = inv; g_wts [2*t+1] = ed * inv;
        int p0 = atomicAdd(&g_cnt[e0], 1); g_list[e0*NSLOT + p0] = 2*t;
        int p1 = atomicAdd(&g_cnt[e1], 1); g_list[e1*NSLOT + p1] = 2*t + 1;
    }
}

__global__ void tilemeta_kernel(){
    if (threadIdx.x == 0){
        int nt = 0;
        for (int e = 0; e < NE; e++){
            int c = g_cnt[e];
            for (int b = 0; b < c; b += 128){
                g_tile_e[nt] = e; g_tile_base[nt] = b; nt++;
            }
        }
        g_ntiles = nt;
    }
}

// ---------------- gateup v2 ----------------
__global__ __launch_bounds__(256, 1) void gateup_kernel(){
    int tileid = blockIdx.y;
    if (tileid >= g_ntiles) return;
    const int e = g_tile_e[tileid];
    const int tbase = g_tile_base[tileid];
    const int cnt = g_cnt[e];
    const int i0 = blockIdx.x << 7;
    extern __shared__ float sm[];
    __shared__ int s_ent[128];
    const int tid = threadIdx.x;
    if (tid < 128){
        int j = tbase + tid;
        s_ent[tid] = (j < cnt) ? g_list[e*NSLOT + j] : -1;
    }
    __syncthreads();
    uint32_t smem_base = (uint32_t)__cvta_generic_to_shared(sm);

    {
        const int rA = tid >> 3;
        const int cc = (tid & 7) << 2;
        const uint32_t ccs = (uint32_t)cc ^ (((uint32_t)(rA & 7)) << 2);
        #pragma unroll
        for (int q = 0; q < 4; q++){
            const int row = rA + 32*q;
            const int ent = s_ent[row];
            const int t = ent >> 1;
            const uint32_t abytes = (ent >= 0) ? 16u : 0u;
            const float* asrc = (ent >= 0)
                ? (g_baseout + (size_t)t*NF + 2*ID + e*NR)
                : g_baseout;
            const float* bsrcg = g_gBc + ((size_t)e*ID + i0 + row)*NR;
            const float* bsrcu = g_uBc + ((size_t)e*ID + i0 + row)*NR;
            #pragma unroll
            for (int ch = 0; ch < 2; ch++){
                const uint32_t dst = ((uint32_t)ch*4096u + (uint32_t)row*32u + ccs)*4u;
                const int kof = ch*32 + cc;
                cp16z(smem_base + dst,                 asrc + kof,      abytes);
                cp16z(smem_base + 32768u + dst,        asrc + EC + kof, abytes);
                cp16 (smem_base + 65536u + dst,        bsrcg + kof);
                cp16 (smem_base + 98304u + dst,        bsrcu + kof);
            }
        }
        cp_commit();
    }
    cp_wait<0>();
    __syncthreads();

    const int wid = tid >> 5, lane = tid & 31;
    const int wm = wid >> 2, wn = wid & 3;
    const int grp = lane >> 2, tig = lane & 3;
    const uint32_t gx = (uint32_t)grp << 2;
    const uint32_t* uAg = (const uint32_t*)sm;
    const uint32_t* uAu = (const uint32_t*)(sm + GU_MATF);
    const uint32_t* uBg = (const uint32_t*)(sm + 2*GU_MATF);
    const uint32_t* uBu = (const uint32_t*)(sm + 3*GU_MATF);

    uint32_t aRow[4], bRow[4];
    #pragma unroll
    for (int i = 0; i < 4; i++) aRow[i] = (uint32_t)(wm*64 + i*16 + grp) * 32u;
    #pragma unroll
    for (int j = 0; j < 4; j++) bRow[j] = (uint32_t)(wn*32 + j*8 + grp) * 32u;

    float accg[4][4][4], accu[4][4][4];
    #pragma unroll
    for (int i = 0; i < 4; i++)
        #pragma unroll
        for (int j = 0; j < 4; j++)
            #pragma unroll
            for (int q = 0; q < 4; q++){ accg[i][j][q]=0.f; accu[i][j][q]=0.f; }

    #pragma unroll
    for (int ch = 0; ch < 2; ch++){
        const uint32_t cb = (uint32_t)ch * 4096u;
        #pragma unroll
        for (int kk = 0; kk < 4; kk++){
            const uint32_t k0 = ((uint32_t)(kk*8) + tig) ^ gx;
            const uint32_t k1 = ((uint32_t)(kk*8) + tig + 4u) ^ gx;
            uint32_t ag[4][4], au[4][4], bg[4][2], bu[4][2];
            #pragma unroll
            for (int i = 0; i < 4; i++){
                ag[i][0] = uAg[cb + aRow[i] + k0];
                ag[i][1] = uAg[cb + aRow[i] + 256u + k0];
                ag[i][2] = uAg[cb + aRow[i] + k1];
                ag[i][3] = uAg[cb + aRow[i] + 256u + k1];
                au[i][0] = uAu[cb + aRow[i] + k0];
                au[i][1] = uAu[cb + aRow[i] + 256u + k0];
                au[i][2] = uAu[cb + aRow[i] + k1];
                au[i][3] = uAu[cb + aRow[i] + 256u + k1];
            }
            #pragma unroll
            for (int j = 0; j < 4; j++){
                bg[j][0] = uBg[cb + bRow[j] + k0];
                bg[j][1] = uBg[cb + bRow[j] + k1];
                bu[j][0] = uBu[cb + bRow[j] + k0];
                bu[j][1] = uBu[cb + bRow[j] + k1];
            }
            #pragma unroll
            for (int i = 0; i < 4; i++)
                #pragma unroll
                for (int j = 0; j < 4; j++){
                    mma_tf32(accg[i][j], ag[i], bg[j]);
                    mma_tf32(accu[i][j], au[i], bu[j]);
                }
        }
    }

    #pragma unroll
    for (int i = 0; i < 4; i++){
        #pragma unroll
        for (int half = 0; half < 2; half++){
            int r = wm*64 + i*16 + grp + half*8;
            int ent = s_ent[r];
            if (ent < 0) continue;
            int t = ent >> 1;
            float w = g_wts[ent];
            const float* brow = g_baseout + (size_t)t*NF;
            float* hrow = g_hs + (size_t)ent*ID;
            #pragma unroll
            for (int j = 0; j < 4; j++){
                int col = i0 + wn*32 + j*8 + (tig << 1);
                float2 bg2 = *(const float2*)(brow + col);
                float2 bu2 = *(const float2*)(brow + ID + col);
                float cg0 = accg[i][j][half*2+0], cg1 = accg[i][j][half*2+1];
                float cu0 = accu[i][j][half*2+0], cu1 = accu[i][j][half*2+1];
                float gate0 = bg2.x + SCALE*cg0, gate1 = bg2.y + SCALE*cg1;
                float up0 = bu2.x + SCALE*cu0,  up1 = bu2.y + SCALE*cu1;
                float h0 = gate0 * (1.f/(1.f+__expf(-gate0))) * up0;
                float h1 = gate1 * (1.f/(1.f+__expf(-gate1))) * up1;
                *(float2*)(hrow + col) = make_float2(f2tf32f(w*h0), f2tf32f(w*h1));
            }
        }
    }
}

// ---------------- grouped corr GEMM ----------------
__global__ __launch_bounds__(128, 2) void corr_kernel(){
    int tileid = blockIdx.y;
    if (tileid >= g_ntiles) return;
    const int e = g_tile_e[tileid];
    const int tbase = g_tile_base[tileid];
    const int cnt = g_cnt[e];
    const int ks = blockIdx.x;
    extern __shared__ float sm[];
    __shared__ int s_ent[128];
    const int tid = threadIdx.x;
    if (tid < 128){
        int j = tbase + tid;
        s_ent[tid] = (j < cnt) ? g_list[e*NSLOT + j] : -1;
    }
    __syncthreads();
    uint32_t smem_base = (uint32_t)__cvta_generic_to_shared(sm);

    const int rA = tid >> 3;
    const int cc = (tid & 7) << 2;
    const uint32_t ccs = (uint32_t)cc ^ (((uint32_t)(rA & 7)) << 2);
    const size_t koff0 = (size_t)ks*CK + cc;

    const float* Asrc[8]; uint32_t Abytes[8];
    #pragma unroll
    for (int q = 0; q < 8; q++){
        int ent = s_ent[rA + 16*q];
        Asrc[q] = (ent >= 0) ? (g_hs + (size_t)ent*ID + koff0) : g_hs;
        Abytes[q] = (ent >= 0) ? 16u : 0u;
    }
    const float* Bsrc[4];
    #pragma unroll
    for (int q = 0; q < 4; q++)
        Bsrc[q] = g_dac + (size_t)(e*NR + rA + 16*q)*ID + koff0;

    uint32_t dstA[8], dstB[4];
    #pragma unroll
    for (int q = 0; q < 8; q++) dstA[q] = ((uint32_t)(rA + 16*q) * 32u + ccs) * 4u;
    #pragma unroll
    for (int q = 0; q < 4; q++) dstB[q] = 16384u + ((uint32_t)(rA + 16*q) * 32u + ccs) * 4u;

    const int nch = CK >> 5;

    #pragma unroll
    for (int s = 0; s < 2; s++){
        uint32_t base = smem_base + (uint32_t)s * C_STAGE_BYTES;
        #pragma unroll
        for (int q = 0; q < 8; q++) cp16z(base + dstA[q], Asrc[q] + (s<<5), Abytes[q]);
        #pragma unroll
        for (int q = 0; q < 4; q++) cp16(base + dstB[q], Bsrc[q] + (s<<5));
        cp_commit();
    }

    const int wid = tid >> 5, lane = tid & 31;
    const int wm = wid >> 1, wn = wid & 1;
    const int grp = lane >> 2, tig = lane & 3;
    const uint32_t gx = (uint32_t)grp << 2;
    uint32_t aRow[4], bRow[4];
    #pragma unroll
    for (int i = 0; i < 4; i++) aRow[i] = (uint32_t)(wm*64 + i*16 + grp) * 32u;
    #pragma unroll
    for (int j = 0; j < 4; j++) bRow[j] = 4096u + (uint32_t)(wn*32 + j*8 + grp) * 32u;

    float acc[4][4][4];
    #pragma unroll
    for (int i = 0; i < 4; i++)
        #pragma unroll
        for (int j = 0; j < 4; j++)
            #pragma unroll
            for (int q = 0; q < 4; q++) acc[i][j][q] = 0.f;

    for (int c = 0; c < nch; c++){
        cp_wait<1>();
        __syncthreads();
        if (c + 2 < nch){
            const int cn = c + 2;
            uint32_t base = smem_base + (uint32_t)(cn % 3) * C_STAGE_BYTES;
            #pragma unroll
            for (int q = 0; q < 8; q++) cp16z(base + dstA[q], Asrc[q] + (cn<<5), Abytes[q]);
            #pragma unroll
            for (int q = 0; q < 4; q++) cp16(base + dstB[q], Bsrc[q] + (cn<<5));
        }
        cp_commit();

        const uint32_t* st = (const uint32_t*)(sm + (size_t)(c % 3) * C_STAGE_FLOATS);
        #pragma unroll
        for (int kk = 0; kk < 4; kk++){
            const uint32_t k0 = ((uint32_t)(kk*8) + tig) ^ gx;
            const uint32_t k1 = ((uint32_t)(kk*8) + tig + 4u) ^ gx;
            uint32_t af[4][4], bf[4][2];
            #pragma unroll
            for (int i = 0; i < 4; i++){
                af[i][0] = st[aRow[i] + k0];
                af[i][1] = st[aRow[i] + 256u + k0];
                af[i][2] = st[aRow[i] + k1];
                af[i][3] = st[aRow[i] + 256u + k1];
            }
            #pragma unroll
            for (int j = 0; j < 4; j++){
                bf[j][0] = st[bRow[j] + k0];
                bf[j][1] = st[bRow[j] + k1];
            }
            #pragma unroll
            for (int i = 0; i < 4; i++)
                #pragma unroll
                for (int j = 0; j < 4; j++)
                    mma_tf32(acc[i][j], af[i], bf[j]);
        }
    }

    #pragma unroll
    for (int i = 0; i < 4; i++){
        #pragma unroll
        for (int half = 0; half < 2; half++){
            int r = wm*64 + i*16 + grp + half*8;
            int ent = s_ent[r];
            if (ent < 0) continue;
            float* crow = g_corrp + ((size_t)ks*NSLOT + ent)*NR;
            #pragma unroll
            for (int j = 0; j < 4; j++){
                int col = wn*32 + j*8 + (tig << 1);
                *(float2*)(crow + col) =
                    make_float2(acc[i][j][half*2+0], acc[i][j][half*2+1]);
            }
        }
    }
}

// ---------------- bcomb ----------------
__global__ void bcomb_kernel(const float* __restrict__ bdw, const float* __restrict__ dB){
    size_t idx = (size_t)blockIdx.x * 256 + threadIdx.x;
    int h = (int)(idx / KDOWN); int k = (int)(idx % KDOWN);
    float v;
    if (k < ID) v = bdw[(size_t)h * ID + k];
    else { int j = k - ID; int e = j >> 6; int r = j & 63;
           v = dB[((size_t)e * HD + h) * NR + r]; }
    g_bcomb[idx] = f2tf32f(v);
}

// hmix head: hs0+hs1
__global__ void addhead_kernel(){
    size_t i4 = ((size_t)blockIdx.x * 256 + threadIdx.x) << 2;
    int t = (int)(i4 / ID); int col = (int)(i4 % ID);
    float4 a = *(const float4*)&g_hs[(size_t)(2*t)*ID + col];
    float4 b = *(const float4*)&g_hs[(size_t)(2*t+1)*ID + col];
    float4 o;
    o.x = f2tf32f(a.x+b.x); o.y = f2tf32f(a.y+b.y);
    o.z = f2tf32f(a.z+b.z); o.w = f2tf32f(a.w+b.w);
    *(float4*)&g_hmixext[(size_t)t * KDOWN + col] = o;
}

// cvec tail
__global__ void cvec_kernel(){
    int idx = blockIdx.x * 256 + threadIdx.x;
    int t = idx >> 9, j = idx & 511;
    int e = j >> 6, r = j & 63;
    float v = 0.f;
    #pragma unroll
    for (int k = 0; k < 2; k++){
        int ent = 2*t + k;
        if (g_eids[ent] == e){
            #pragma unroll
            for (int s = 0; s < 4; s++)
                v += g_corrp[((size_t)s*NSLOT + ent)*NR + r];
        }
    }
    g_hmixext[(size_t)t * KDOWN + ID + j] = f2tf32f(SCALE * v);
}

// ---------------- launch ----------------
static void launch_gemm_s(cudaStream_t st, const float* A, const float* B, float* C,
                          int M, int N, int K, int lda, int ldb, int roundN, int accum){
    dim3 grid(N / BN, M / BM);
    gemm_tf32<<<grid, 128, SMEM_BYTES, st>>>(A, B, C, M, N, K, lda, ldb, roundN, accum);
}
static void launch_conv_s(cudaStream_t st, const float* in, float* out, size_t n){
    conv_kernel<<<(unsigned)((n / 4) / 256), 256, 0, st>>>(in, out);
}

extern "C" void kernel_launch(void* const* d_in, const int* in_sizes, int n_in,
                              void* d_out, int out_size){
    const float* x      = (const float*)d_in[0];
    const float* conf_w = (const float*)d_in[1];
    const float* conf_b = (const float*)d_in[2];
    const float* wealth = (const float*)d_in[3];
    const float* bgw    = (const float*)d_in[4];
    const float* buw    = (const float*)d_in[5];
    const float* bdw    = (const float*)d_in[6];
    const float* gA     = (const float*)d_in[7];
    const float* gB     = (const float*)d_in[8];
    const float* uA     = (const float*)d_in[9];
    const float* uB     = (const float*)d_in[10];
    const float* dA     = (const float*)d_in[11];
    const float* dB     = (const float*)d_in[12];
    float* out = (float*)d_out;

    static bool init_done = false;
    static cudaStream_t s1, s2;
    static cudaEvent_t evFork, evS1, evS2, evGate, evAdd, evMain;
    if (!init_done){
        cudaFuncSetAttribute(gemm_tf32, cudaFuncAttributeMaxDynamicSharedMemorySize, SMEM_BYTES);
        cudaFuncSetAttribute(gateup_kernel, cudaFuncAttributeMaxDynamicSharedMemorySize, GU_SMEM_BYTES);
        cudaFuncSetAttribute(corr_kernel, cudaFuncAttributeMaxDynamicSharedMemorySize, C_SMEM_BYTES);
        cudaStreamCreateWithFlags(&s1, cudaStreamNonBlocking);
        cudaStreamCreateWithFlags(&s2, cudaStreamNonBlocking);
        cudaEventCreateWithFlags(&evFork, cudaEventDisableTiming);
        cudaEventCreateWithFlags(&evS1,   cudaEventDisableTiming);
        cudaEventCreateWithFlags(&evS2,   cudaEventDisableTiming);
        cudaEventCreateWithFlags(&evGate, cudaEventDisableTiming);
        cudaEventCreateWithFlags(&evAdd,  cudaEventDisableTiming);
        cudaEventCreateWithFlags(&evMain, cudaEventDisableTiming);
        init_done = true;
    }

    float *p_xc, *p_fusedW, *p_baseout, *p_hmixext, *p_dac, *p_bcomb, *p_gBc, *p_uBc;
    cudaGetSymbolAddress((void**)&p_xc,      g_xc);
    cudaGetSymbolAddress((void**)&p_fusedW,  g_fusedW);
    cudaGetSymbolAddress((void**)&p_baseout, g_baseout);
    cudaGetSymbolAddress((void**)&p_hmixext, g_hmixext);
    cudaGetSymbolAddress((void**)&p_dac,     g_dac);
    cudaGetSymbolAddress((void**)&p_bcomb,   g_bcomb);
    cudaGetSymbolAddress((void**)&p_gBc,     g_gBc);
    cudaGetSymbolAddress((void**)&p_uBc,     g_uBc);

    cudaStream_t s0 = 0;

    cudaEventRecord(evFork, s0);
    cudaStreamWaitEvent(s1, evFork, 0);
    cudaStreamWaitEvent(s2, evFork, 0);

    // s0: routing path + x conversion
    zero_cnt_kernel<<<1, 32, 0, s0>>>();
    routing_kernel<<<NTOK, 256, 0, s0>>>(x, conf_w, conf_b, wealth);
    tilemeta_kernel<<<1, 32, 0, s0>>>();
    launch_conv_s(s0, x, p_xc, (size_t)NTOK*HD);

    // s1: fusedW conversions
    launch_conv_s(s1, bgw, p_fusedW,                        (size_t)ID*HD);
    launch_conv_s(s1, buw, p_fusedW + (size_t)ID*HD,        (size_t)ID*HD);
    launch_conv_s(s1, gA,  p_fusedW + (size_t)2*ID*HD,      (size_t)EC*HD);
    launch_conv_s(s1, uA,  p_fusedW + (size_t)(2*ID+EC)*HD, (size_t)EC*HD);
    cudaEventRecord(evS1, s1);

    // s2: mid/down operand prep (hidden under x-GEMM)
    launch_conv_s(s2, gB, p_gBc, (size_t)NE*ID*NR);
    launch_conv_s(s2, uB, p_uBc, (size_t)NE*ID*NR);
    launch_conv_s(s2, dA, p_dac, (size_t)EC*ID);
    bcomb_kernel<<<((size_t)HD*KDOWN)/256, 256, 0, s2>>>(bdw, dB);
    cudaEventRecord(evS2, s2);

    // x-side fused GEMM
    cudaStreamWaitEvent(s0, evS1, 0);
    launch_gemm_s(s0, p_xc, p_fusedW, p_baseout, NTOK, NF, HD, HD, HD, 2*ID, 0);

    // gateup v2
    cudaStreamWaitEvent(s0, evS2, 0);
    gateup_kernel<<<dim3(ID/128, MAXTILE), 256, GU_SMEM_BYTES, s0>>>();
    cudaEventRecord(evGate, s0);

    // s1: addhead -> main down GEMM (K=ID) while s0 does corr+cvec
    cudaStreamWaitEvent(s1, evGate, 0);
    addhead_kernel<<<(NTOK*ID/4)/256, 256, 0, s1>>>();
    cudaEventRecord(evAdd, s1);
    launch_gemm_s(s1, p_hmixext, p_bcomb, out, NTOK, HD, ID, KDOWN, KDOWN, 1<<30, 0);
    cudaEventRecord(evMain, s1);

    // s0: down-LoRA correction path (overlapped with main down GEMM)
    corr_kernel<<<dim3(4, MAXTILE), 128, C_SMEM_BYTES, s0>>>();
    cvec_kernel<<<(NTOK*EC)/256, 256, 0, s0>>>();

    // accumulating tail down GEMM: out += cvec @ dBall^T
    cudaStreamWaitEvent(s0, evMain, 0);
    launch_gemm_s(s0, p_hmixext + ID, p_bcomb + ID, out, NTOK, HD, EC, KDOWN, KDOWN, 1<<30, 1);
}

// round 16
// speedup vs baseline: 1.8502x; 1.7520x over previous
#include <cuda_runtime.h>
#include <cuda_fp16.h>
#include <cstdint>
#include <math.h>

#define NTOK 2048
#define HD   2048
#define ID   7168
#define NE   8
#define NR   64
#define EC   (NE*NR)       // 512
#define KDOWN (ID+EC)      // 7680
#define NF   (2*ID+2*EC)   // 15360
#define SCALE 0.25f
#define NSLOT (2*NTOK)     // 4096
#define MAXTILE 40

// fp16 GEMM: 128x128x64(halves), 3 stages, 128 threads (4 warps, 2x2 of 64x64)
#define BM 128
#define BN 128
#define STAGES 3
#define STAGE_U32 8192               // A 4096 + B 4096 (u32 = half2)
#define STAGE_BYTES 32768
#define SMEM_BYTES (STAGES*STAGE_BYTES)   // 98304

// gateup: 4 matrices x (128 x 64 halves) = 64KB
#define GU_SMEM_BYTES 65536

// corr: 128x64x64(halves), 3 stages: A 16KB + B 8KB per stage
#define CK 1792                      // halves per split
#define C_STAGE_U32 6144
#define C_STAGE_BYTES 24576
#define C_SMEM_BYTES (3*C_STAGE_BYTES)

// ---------------- scratch ----------------
__device__ __half g_xch   [(size_t)NTOK*HD];
__device__ __half g_fWh   [(size_t)NF*HD];
__device__ float  g_baseout[(size_t)NTOK*NF];     // fp32 (basegate|baseup|tg|tu)
__device__ __half g_tguh  [(size_t)NTOK*2*EC];    // fp16 copy of tg|tu
__device__ __half g_hsh   [(size_t)NSLOT*ID];
__device__ __half g_hmixh [(size_t)NTOK*KDOWN];
__device__ float  g_corrp [(size_t)4*NSLOT*NR];
__device__ __half g_bcombh[(size_t)HD*KDOWN];
__device__ __half g_dach  [(size_t)EC*ID];
__device__ __half g_gBh   [(size_t)NE*ID*NR];
__device__ __half g_uBh   [(size_t)NE*ID*NR];
__device__ int    g_eids  [NSLOT];
__device__ float  g_wts   [NSLOT];
__device__ int    g_cnt   [NE];
__device__ int    g_list  [NE*NSLOT];
__device__ int    g_tile_e[MAXTILE+8];
__device__ int    g_tile_base[MAXTILE+8];
__device__ int    g_ntiles;

// ---------------- helpers ----------------
__device__ __forceinline__ void mma_f16(float* c, const uint32_t* a, const uint32_t* b){
    asm volatile(
        "mma.sync.aligned.m16n8k16.row.col.f32.f16.f16.f32 "
        "{%0,%1,%2,%3}, {%4,%5,%6,%7}, {%8,%9}, {%0,%1,%2,%3};"
        : "+f"(c[0]), "+f"(c[1]), "+f"(c[2]), "+f"(c[3])
        : "r"(a[0]), "r"(a[1]), "r"(a[2]), "r"(a[3]), "r"(b[0]), "r"(b[1]));
}
__device__ __forceinline__ void cp16(uint32_t smaddr, const void* g){
    asm volatile("cp.async.cg.shared.global [%0], [%1], 16;" :: "r"(smaddr), "l"(g));
}
__device__ __forceinline__ void cp16z(uint32_t smaddr, const void* g, uint32_t bytes){
    asm volatile("cp.async.cg.shared.global [%0], [%1], 16, %2;"
                 :: "r"(smaddr), "l"(g), "r"(bytes));
}
__device__ __forceinline__ void cp_commit(){
    asm volatile("cp.async.commit_group;" ::: "memory");
}
template<int N> __device__ __forceinline__ void cp_wait(){
    asm volatile("cp.async.wait_group %0;" :: "n"(N) : "memory");
}

// ---------------- fp16 GEMM: C[M,N] = A[M,K]*B[N,K]^T (fp32 out) ----------------
// K, lda, ldb in halves. M%128==0, N%128==0, K%64==0.
// If C2 != null: cols >= c2base additionally stored as fp16 at C2[row*c2ld + col-c2base].
__global__ __launch_bounds__(128, 2) void gemm_h16(
        const __half* __restrict__ A, const __half* __restrict__ B,
        float* __restrict__ C, int M, int N, int K, int lda, int ldb,
        __half* __restrict__ C2, int c2base, int c2ld){
    extern __shared__ uint32_t sm[];
    const int tid = threadIdx.x;
    const int wid = tid >> 5, lane = tid & 31;
    const int wm = wid >> 1, wn = wid & 1;
    const int grp = lane >> 2, tig = lane & 3;
    const int m0 = blockIdx.y * BM, n0 = blockIdx.x * BN;
    uint32_t smem_base = (uint32_t)__cvta_generic_to_shared(sm);

    const int rA = tid >> 3;               // 0..15
    const int cc = (tid & 7) << 2;         // u32 col 0..28
    const uint32_t ccs = (uint32_t)cc ^ (((uint32_t)(rA & 7)) << 2);
    const int ch = cc << 1;                // half offset within row
    const __half* Agp = A + (size_t)(m0 + rA) * lda + ch;
    const __half* Bgp = B + (size_t)(n0 + rA) * ldb + ch;
    const size_t rstepA = (size_t)16 * lda;
    const size_t rstepB = (size_t)16 * ldb;

    uint32_t dstA[8], dstB[8];
    #pragma unroll
    for (int q = 0; q < 8; q++){
        dstA[q] = ((uint32_t)(rA + 16*q) * 32u + ccs) * 4u;
        dstB[q] = 16384u + dstA[q];
    }
    const int nch = K >> 6;

    #pragma unroll
    for (int s = 0; s < STAGES-1; s++){
        if (s < nch){
            uint32_t base = smem_base + (uint32_t)s * STAGE_BYTES;
            const __half* ag = Agp + (s << 6);
            const __half* bg = Bgp + (s << 6);
            #pragma unroll
            for (int q = 0; q < 8; q++) cp16(base + dstA[q], ag + rstepA * q);
            #pragma unroll
            for (int q = 0; q < 8; q++) cp16(base + dstB[q], bg + rstepB * q);
        }
        cp_commit();
    }

    const uint32_t gx = (uint32_t)grp << 2;
    uint32_t aRow[4], bRow[8];
    #pragma unroll
    for (int i = 0; i < 4; i++) aRow[i] = (uint32_t)(wm*64 + i*16 + grp) * 32u;
    #pragma unroll
    for (int j = 0; j < 8; j++) bRow[j] = 4096u + (uint32_t)(wn*64 + j*8 + grp) * 32u;

    float acc[4][8][4];
    #pragma unroll
    for (int i = 0; i < 4; i++)
        #pragma unroll
        for (int j = 0; j < 8; j++)
            #pragma unroll
            for (int q = 0; q < 4; q++) acc[i][j][q] = 0.f;

    for (int c = 0; c < nch; c++){
        cp_wait<STAGES-2>();
        __syncthreads();
        if (c + STAGES-1 < nch){
            const int cn = c + STAGES-1;
            uint32_t base = smem_base + (uint32_t)(cn % STAGES) * STAGE_BYTES;
            const __half* ag = Agp + (cn << 6);
            const __half* bg = Bgp + (cn << 6);
            #pragma unroll
            for (int q = 0; q < 8; q++) cp16(base + dstA[q], ag + rstepA * q);
            #pragma unroll
            for (int q = 0; q < 8; q++) cp16(base + dstB[q], bg + rstepB * q);
        }
        cp_commit();

        const uint32_t* st = sm + (size_t)(c % STAGES) * STAGE_U32;
        #pragma unroll
        for (int kk = 0; kk < 4; kk++){
            const uint32_t k0 = ((uint32_t)(kk*8) + tig) ^ gx;
            const uint32_t k1 = ((uint32_t)(kk*8) + tig + 4u) ^ gx;
            uint32_t af[4][4], bf[8][2];
            #pragma unroll
            for (int i = 0; i < 4; i++){
                af[i][0] = st[aRow[i] + k0];
                af[i][1] = st[aRow[i] + 256u + k0];
                af[i][2] = st[aRow[i] + k1];
                af[i][3] = st[aRow[i] + 256u + k1];
            }
            #pragma unroll
            for (int j = 0; j < 8; j++){
                bf[j][0] = st[bRow[j] + k0];
                bf[j][1] = st[bRow[j] + k1];
            }
            #pragma unroll
            for (int i = 0; i < 4; i++)
                #pragma unroll
                for (int j = 0; j < 8; j++)
                    mma_f16(acc[i][j], af[i], bf[j]);
        }
    }

    #pragma unroll
    for (int i = 0; i < 4; i++){
        int r0 = m0 + wm*64 + i*16 + grp;
        float* cr0 = C + (size_t)r0 * N;
        float* cr1 = C + (size_t)(r0 + 8) * N;
        #pragma unroll
        for (int j = 0; j < 8; j++){
            int col = n0 + wn*64 + j*8 + (tig << 1);
            float v0 = acc[i][j][0], v1 = acc[i][j][1];
            float v2 = acc[i][j][2], v3 = acc[i][j][3];
            *(float2*)(cr0 + col) = make_float2(v0, v1);
            *(float2*)(cr1 + col) = make_float2(v2, v3);
            if (C2 && col >= c2base){
                int c2 = col - c2base;
                *(__half2*)(C2 + (size_t)r0 * c2ld + c2)      = __floats2half2_rn(v0, v1);
                *(__half2*)(C2 + (size_t)(r0+8) * c2ld + c2)  = __floats2half2_rn(v2, v3);
            }
        }
    }
}

// ---------------- fp32 -> fp16 conversion (8 elems/thread) ----------------
__global__ void convh_kernel(const float* __restrict__ in, __half* __restrict__ out){
    size_t i8 = ((size_t)blockIdx.x * 256 + threadIdx.x) << 3;
    float4 a = *(const float4*)(in + i8);
    float4 b = *(const float4*)(in + i8 + 4);
    __half2 h0 = __floats2half2_rn(a.x, a.y);
    __half2 h1 = __floats2half2_rn(a.z, a.w);
    __half2 h2 = __floats2half2_rn(b.x, b.y);
    __half2 h3 = __floats2half2_rn(b.z, b.w);
    uint4 o;
    o.x = *(uint32_t*)&h0; o.y = *(uint32_t*)&h1;
    o.z = *(uint32_t*)&h2; o.w = *(uint32_t*)&h3;
    *(uint4*)(out + i8) = o;
}

// ---------------- routing + scatter ----------------
__global__ void zero_cnt_kernel(){ if (threadIdx.x < NE) g_cnt[threadIdx.x] = 0; }

__global__ void routing_kernel(const float* __restrict__ x,
                               const float* __restrict__ cw,
                               const float* __restrict__ cb,
                               const float* __restrict__ wealth){
    int t = blockIdx.x;
    int w = threadIdx.x >> 5, lane = threadIdx.x & 31;
    const float* xr = x + (size_t)t * HD;
    const float* cr = cw + (size_t)w * HD;
    float s = 0.f;
    for (int j = lane; j < HD; j += 32) s += xr[j] * cr[j];
    #pragma unroll
    for (int o = 16; o; o >>= 1) s += __shfl_down_sync(0xffffffffu, s, o);
    __shared__ float bids[NE];
    if (lane == 0){
        float conf = 1.f / (1.f + expf(-(s + cb[w])));
        bids[w] = conf * wealth[w];
    }
    __syncthreads();
    if (threadIdx.x == 0){
        int e0 = 0; float b0 = bids[0];
        for (int e = 1; e < NE; e++) if (bids[e] > b0){ b0 = bids[e]; e0 = e; }
        int e1 = -1; float b1 = -1e30f;
        for (int e = 0; e < NE; e++) if (e != e0 && bids[e] > b1){ b1 = bids[e]; e1 = e; }
        float ed = expf(b1 - b0);
        float inv = 1.f / (1.f + ed);
        g_eids[2*t] = e0; g_eids[2*t+1] = e1;
        g_wts [2*t] = inv; g_wts [2*t+1] = ed * inv;
        int p0 = atomicAdd(&g_cnt[e0], 1); g_list[e0*NSLOT + p0] = 2*t;
        int p1 = atomicAdd(&g_cnt[e1], 1); g_list[e1*NSLOT + p1] = 2*t + 1;
    }
}

__global__ void tilemeta_kernel(){
    if (threadIdx.x == 0){
        int nt = 0;
        for (int e = 0; e < NE; e++){
            int c = g_cnt[e];
            for (int b = 0; b < c; b += 128){
                g_tile_e[nt] = e; g_tile_base[nt] = b; nt++;
            }
        }
        g_ntiles = nt;
    }
}

// ---------------- gateup (fp16): 128 slots x 128 i-cols, K=64 ----------------
// SMEM: Ag[0,16K) Au[16K,32K) Bg[32K,48K) Bu[48K,64K); each 128 rows x 64 halves.
__global__ __launch_bounds__(256, 2) void gateup_kernel(){
    int tileid = blockIdx.y;
    if (tileid >= g_ntiles) return;
    const int e = g_tile_e[tileid];
    const int tbase = g_tile_base[tileid];
    const int cnt = g_cnt[e];
    const int i0 = blockIdx.x << 7;
    extern __shared__ uint32_t sm[];
    __shared__ int s_ent[128];
    const int tid = threadIdx.x;
    if (tid < 128){
        int j = tbase + tid;
        s_ent[tid] = (j < cnt) ? g_list[e*NSLOT + j] : -1;
    }
    __syncthreads();
    uint32_t smem_base = (uint32_t)__cvta_generic_to_shared(sm);

    {
        const int rA = tid >> 3;              // 0..31
        const int cc = (tid & 7) << 2;        // u32 col 0..28
        const uint32_t ccs = (uint32_t)cc ^ (((uint32_t)(rA & 7)) << 2);
        const int ch = cc << 1;               // half offset
        #pragma unroll
        for (int q = 0; q < 4; q++){
            const int row = rA + 32*q;
            const int ent = s_ent[row];
            const int t = ent >> 1;
            const uint32_t abytes = (ent >= 0) ? 16u : 0u;
            const __half* asrc = (ent >= 0)
                ? (g_tguh + (size_t)t*(2*EC) + e*NR + ch)
                : g_tguh;
            const __half* bsrcg = g_gBh + ((size_t)e*ID + i0 + row)*NR + ch;
            const __half* bsrcu = g_uBh + ((size_t)e*ID + i0 + row)*NR + ch;
            const uint32_t dst = ((uint32_t)row*32u + ccs)*4u;
            cp16z(smem_base + dst,            asrc,        abytes);   // Ag (tg)
            cp16z(smem_base + 16384u + dst,   asrc + EC,   abytes);   // Au (tu)
            cp16 (smem_base + 32768u + dst,   bsrcg);
            cp16 (smem_base + 49152u + dst,   bsrcu);
        }
        cp_commit();
    }
    cp_wait<0>();
    __syncthreads();

    const int wid = tid >> 5, lane = tid & 31;
    const int wm = wid >> 2, wn = wid & 3;    // 2x4 warps, 64x32 tiles
    const int grp = lane >> 2, tig = lane & 3;
    const uint32_t gx = (uint32_t)grp << 2;
    const uint32_t* uAg = sm;
    const uint32_t* uAu = sm + 4096;
    const uint32_t* uBg = sm + 8192;
    const uint32_t* uBu = sm + 12288;

    uint32_t aRow[4], bRow[4];
    #pragma unroll
    for (int i = 0; i < 4; i++) aRow[i] = (uint32_t)(wm*64 + i*16 + grp) * 32u;
    #pragma unroll
    for (int j = 0; j < 4; j++) bRow[j] = (uint32_t)(wn*32 + j*8 + grp) * 32u;

    float accg[4][4][4], accu[4][4][4];
    #pragma unroll
    for (int i = 0; i < 4; i++)
        #pragma unroll
        for (int j = 0; j < 4; j++)
            #pragma unroll
            for (int q = 0; q < 4; q++){ accg[i][j][q]=0.f; accu[i][j][q]=0.f; }

    #pragma unroll
    for (int kk = 0; kk < 4; kk++){
        const uint32_t k0 = ((uint32_t)(kk*8) + tig) ^ gx;
        const uint32_t k1 = ((uint32_t)(kk*8) + tig + 4u) ^ gx;
        uint32_t ag[4][4], au[4][4], bg[4][2], bu[4][2];
        #pragma unroll
        for (int i = 0; i < 4; i++){
            ag[i][0] = uAg[aRow[i] + k0];
            ag[i][1] = uAg[aRow[i] + 256u + k0];
            ag[i][2] = uAg[aRow[i] + k1];
            ag[i][3] = uAg[aRow[i] + 256u + k1];
            au[i][0] = uAu[aRow[i] + k0];
            au[i][1] = uAu[aRow[i] + 256u + k0];
            au[i][2] = uAu[aRow[i] + k1];
            au[i][3] = uAu[aRow[i] + 256u + k1];
        }
        #pragma unroll
        for (int j = 0; j < 4; j++){
            bg[j][0] = uBg[bRow[j] + k0];
            bg[j][1] = uBg[bRow[j] + k1];
            bu[j][0] = uBu[bRow[j] + k0];
            bu[j][1] = uBu[bRow[j] + k1];
        }
        #pragma unroll
        for (int i = 0; i < 4; i++)
            #pragma unroll
            for (int j = 0; j < 4; j++){
                mma_f16(accg[i][j], ag[i], bg[j]);
                mma_f16(accu[i][j], au[i], bu[j]);
            }
    }

    // epilogue: base add (fp32) + silu*up + weight, write hs fp16
    #pragma unroll
    for (int i = 0; i < 4; i++){
        #pragma unroll
        for (int half_ = 0; half_ < 2; half_++){
            int r = wm*64 + i*16 + grp + half_*8;
            int ent = s_ent[r];
            if (ent < 0) continue;
            int t = ent >> 1;
            float w = g_wts[ent];
            const float* brow = g_baseout + (size_t)t*NF;
            __half* hrow = g_hsh + (size_t)ent*ID;
            #pragma unroll
            for (int j = 0; j < 4; j++){
                int col = i0 + wn*32 + j*8 + (tig << 1);
                float2 bg2 = *(const float2*)(brow + col);
                float2 bu2 = *(const float2*)(brow + ID + col);
                float cg0 = accg[i][j][half_*2+0], cg1 = accg[i][j][half_*2+1];
                float cu0 = accu[i][j][half_*2+0], cu1 = accu[i][j][half_*2+1];
                float gate0 = bg2.x + SCALE*cg0, gate1 = bg2.y + SCALE*cg1;
                float up0 = bu2.x + SCALE*cu0,  up1 = bu2.y + SCALE*cu1;
                float h0 = gate0 * (1.f/(1.f+__expf(-gate0))) * up0;
                float h1 = gate1 * (1.f/(1.f+__expf(-gate1))) * up1;
                *(__half2*)(hrow + col) = __floats2half2_rn(w*h0, w*h1);
            }
        }
    }
}

// ---------------- grouped corr GEMM (fp16 in, fp32 out) ----------------
__global__ __launch_bounds__(128, 2) void corr_kernel(){
    int tileid = blockIdx.y;
    if (tileid >= g_ntiles) return;
    const int e = g_tile_e[tileid];
    const int tbase = g_tile_base[tileid];
    const int cnt = g_cnt[e];
    const int ks = blockIdx.x;
    extern __shared__ uint32_t sm[];
    __shared__ int s_ent[128];
    const int tid = threadIdx.x;
    if (tid < 128){
        int j = tbase + tid;
        s_ent[tid] = (j < cnt) ? g_list[e*NSLOT + j] : -1;
    }
    __syncthreads();
    uint32_t smem_base = (uint32_t)__cvta_generic_to_shared(sm);

    const int rA = tid >> 3;
    const int cc = (tid & 7) << 2;
    const uint32_t ccs = (uint32_t)cc ^ (((uint32_t)(rA & 7)) << 2);
    const int ch = cc << 1;
    const size_t koff0 = (size_t)ks*CK + ch;

    const __half* Asrc[8]; uint32_t Abytes[8];
    #pragma unroll
    for (int q = 0; q < 8; q++){
        int ent = s_ent[rA + 16*q];
        Asrc[q] = (ent >= 0) ? (g_hsh + (size_t)ent*ID + koff0) : g_hsh;
        Abytes[q] = (ent >= 0) ? 16u : 0u;
    }
    const __half* Bsrc[4];
    #pragma unroll
    for (int q = 0; q < 4; q++)
        Bsrc[q] = g_dach + (size_t)(e*NR + rA + 16*q)*ID + koff0;

    uint32_t dstA[8], dstB[4];
    #pragma unroll
    for (int q = 0; q < 8; q++) dstA[q] = ((uint32_t)(rA + 16*q) * 32u + ccs) * 4u;
    #pragma unroll
    for (int q = 0; q < 4; q++) dstB[q] = 16384u + ((uint32_t)(rA + 16*q) * 32u + ccs) * 4u;

    const int nch = CK >> 6;   // 28

    #pragma unroll
    for (int s = 0; s < 2; s++){
        uint32_t base = smem_base + (uint32_t)s * C_STAGE_BYTES;
        #pragma unroll
        for (int q = 0; q < 8; q++) cp16z(base + dstA[q], Asrc[q] + (s<<6), Abytes[q]);
        #pragma unroll
        for (int q = 0; q < 4; q++) cp16(base + dstB[q], Bsrc[q] + (s<<6));
        cp_commit();
    }

    const int wid = tid >> 5, lane = tid & 31;
    const int wm = wid >> 1, wn = wid & 1;
    const int grp = lane >> 2, tig = lane & 3;
    const uint32_t gx = (uint32_t)grp << 2;
    uint32_t aRow[4], bRow[4];
    #pragma unroll
    for (int i = 0; i < 4; i++) aRow[i] = (uint32_t)(wm*64 + i*16 + grp) * 32u;
    #pragma unroll
    for (int j = 0; j < 4; j++) bRow[j] = 4096u + (uint32_t)(wn*32 + j*8 + grp) * 32u;

    float acc[4][4][4];
    #pragma unroll
    for (int i = 0; i < 4; i++)
        #pragma unroll
        for (int j = 0; j < 4; j++)
            #pragma unroll
            for (int q = 0; q < 4; q++) acc[i][j][q] = 0.f;

    for (int c = 0; c < nch; c++){
        cp_wait<1>();
        __syncthreads();
        if (c + 2 < nch){
            const int cn = c + 2;
            uint32_t base = smem_base + (uint32_t)(cn % 3) * C_STAGE_BYTES;
            #pragma unroll
            for (int q = 0; q < 8; q++) cp16z(base + dstA[q], Asrc[q] + (cn<<6), Abytes[q]);
            #pragma unroll
            for (int q = 0; q < 4; q++) cp16(base + dstB[q], Bsrc[q] + (cn<<6));
        }
        cp_commit();

        const uint32_t* st = sm + (size_t)(c % 3) * C_STAGE_U32;
        #pragma unroll
        for (int kk = 0; kk < 4; kk++){
            const uint32_t k0 = ((uint32_t)(kk*8) + tig) ^ gx;
            const uint32_t k1 = ((uint32_t)(kk*8) + tig + 4u) ^ gx;
            uint32_t af[4][4], bf[4][2];
            #pragma unroll
            for (int i = 0; i < 4; i++){
                af[i][0] = st[aRow[i] + k0];
                af[i][1] = st[aRow[i] + 256u + k0];
                af[i][2] = st[aRow[i] + k1];
                af[i][3] = st[aRow[i] + 256u + k1];
            }
            #pragma unroll
            for (int j = 0; j < 4; j++){
                bf[j][0] = st[bRow[j] + k0];
                bf[j][1] = st[bRow[j] + k1];
            }
            #pragma unroll
            for (int i = 0; i < 4; i++)
                #pragma unroll
                for (int j = 0; j < 4; j++)
                    mma_f16(acc[i][j], af[i], bf[j]);
        }
    }

    #pragma unroll
    for (int i = 0; i < 4; i++){
        #pragma unroll
        for (int half_ = 0; half_ < 2; half_++){
            int r = wm*64 + i*16 + grp + half_*8;
            int ent = s_ent[r];
            if (ent < 0) continue;
            float* crow = g_corrp + ((size_t)ks*NSLOT + ent)*NR;
            #pragma unroll
            for (int j = 0; j < 4; j++){
                int col = wn*32 + j*8 + (tig << 1);
                *(float2*)(crow + col) =
                    make_float2(acc[i][j][half_*2+0], acc[i][j][half_*2+1]);
            }
        }
    }
}

// ---------------- bcomb: [bdw | dB repack] -> fp16 ----------------
__global__ void bcomb_kernel(const float* __restrict__ bdw, const float* __restrict__ dB){
    size_t idx = (size_t)blockIdx.x * 256 + threadIdx.x;
    int h = (int)(idx / KDOWN); int k = (int)(idx % KDOWN);
    float v;
    if (k < ID) v = bdw[(size_t)h * ID + k];
    else { int j = k - ID; int e = j >> 6; int r = j & 63;
           v = dB[((size_t)e * HD + h) * NR + r]; }
    g_bcombh[idx] = __float2half_rn(v);
}

// hmix head: hs0+hs1 -> fp16
__global__ void addhead_kernel(){
    size_t i8 = ((size_t)blockIdx.x * 256 + threadIdx.x) << 3;
    int t = (int)(i8 / ID); int col = (int)(i8 % ID);
    const __half2* a = (const __half2*)(g_hsh + (size_t)(2*t)*ID + col);
    const __half2* b = (const __half2*)(g_hsh + (size_t)(2*t+1)*ID + col);
    __half2* o = (__half2*)(g_hmixh + (size_t)t * KDOWN + col);
    #pragma unroll
    for (int q = 0; q < 4; q++){
        float2 fa = __half22float2(a[q]);
        float2 fb = __half22float2(b[q]);
        o[q] = __floats2half2_rn(fa.x + fb.x, fa.y + fb.y);
    }
}

// cvec tail -> fp16
__global__ void cvec_kernel(){
    int idx = blockIdx.x * 256 + threadIdx.x;
    int t = idx >> 9, j = idx & 511;
    int e = j >> 6, r = j & 63;
    float v = 0.f;
    #pragma unroll
    for (int k = 0; k < 2; k++){
        int ent = 2*t + k;
        if (g_eids[ent] == e){
            #pragma unroll
            for (int s = 0; s < 4; s++)
                v += g_corrp[((size_t)s*NSLOT + ent)*NR + r];
        }
    }
    g_hmixh[(size_t)t * KDOWN + ID + j] = __float2half_rn(SCALE * v);
}

// ---------------- launch ----------------
static void launch_gemm_s(cudaStream_t st, const __half* A, const __half* B, float* C,
                          int M, int N, int K, int lda, int ldb,
                          __half* C2, int c2base, int c2ld){
    dim3 grid(N / BN, M / BM);
    gemm_h16<<<grid, 128, SMEM_BYTES, st>>>(A, B, C, M, N, K, lda, ldb, C2, c2base, c2ld);
}
static void launch_convh_s(cudaStream_t st, const float* in, __half* out, size_t n){
    convh_kernel<<<(unsigned)((n / 8) / 256), 256, 0, st>>>(in, out);
}

extern "C" void kernel_launch(void* const* d_in, const int* in_sizes, int n_in,
                              void* d_out, int out_size){
    const float* x      = (const float*)d_in[0];
    const float* conf_w = (const float*)d_in[1];
    const float* conf_b = (const float*)d_in[2];
    const float* wealth = (const float*)d_in[3];
    const float* bgw    = (const float*)d_in[4];
    const float* buw    = (const float*)d_in[5];
    const float* bdw    = (const float*)d_in[6];
    const float* gA     = (const float*)d_in[7];
    const float* gB     = (const float*)d_in[8];
    const float* uA     = (const float*)d_in[9];
    const float* uB     = (const float*)d_in[10];
    const float* dA     = (const float*)d_in[11];
    const float* dB     = (const float*)d_in[12];
    float* out = (float*)d_out;

    static bool init_done = false;
    static cudaStream_t s1, s2;
    static cudaEvent_t evFork, evS1, evS2, evGate, evAdd;
    if (!init_done){
        cudaFuncSetAttribute(gemm_h16, cudaFuncAttributeMaxDynamicSharedMemorySize, SMEM_BYTES);
        cudaFuncSetAttribute(gateup_kernel, cudaFuncAttributeMaxDynamicSharedMemorySize, GU_SMEM_BYTES);
        cudaFuncSetAttribute(corr_kernel, cudaFuncAttributeMaxDynamicSharedMemorySize, C_SMEM_BYTES);
        cudaStreamCreateWithFlags(&s1, cudaStreamNonBlocking);
        cudaStreamCreateWithFlags(&s2, cudaStreamNonBlocking);
        cudaEventCreateWithFlags(&evFork, cudaEventDisableTiming);
        cudaEventCreateWithFlags(&evS1,   cudaEventDisableTiming);
        cudaEventCreateWithFlags(&evS2,   cudaEventDisableTiming);
        cudaEventCreateWithFlags(&evGate, cudaEventDisableTiming);
        cudaEventCreateWithFlags(&evAdd,  cudaEventDisableTiming);
        init_done = true;
    }

    __half *p_xch, *p_fWh, *p_tguh, *p_hmixh, *p_bcombh, *p_dach, *p_gBh, *p_uBh;
    float *p_baseout;
    cudaGetSymbolAddress((void**)&p_xch,     g_xch);
    cudaGetSymbolAddress((void**)&p_fWh,     g_fWh);
    cudaGetSymbolAddress((void**)&p_baseout, g_baseout);
    cudaGetSymbolAddress((void**)&p_tguh,    g_tguh);
    cudaGetSymbolAddress((void**)&p_hmixh,   g_hmixh);
    cudaGetSymbolAddress((void**)&p_bcombh,  g_bcombh);
    cudaGetSymbolAddress((void**)&p_dach,    g_dach);
    cudaGetSymbolAddress((void**)&p_gBh,     g_gBh);
    cudaGetSymbolAddress((void**)&p_uBh,     g_uBh);

    cudaStream_t s0 = 0;

    cudaEventRecord(evFork, s0);
    cudaStreamWaitEvent(s1, evFork, 0);
    cudaStreamWaitEvent(s2, evFork, 0);

    // s0: routing path + x conversion
    zero_cnt_kernel<<<1, 32, 0, s0>>>();
    routing_kernel<<<NTOK, 256, 0, s0>>>(x, conf_w, conf_b, wealth);
    tilemeta_kernel<<<1, 32, 0, s0>>>();
    launch_convh_s(s0, x, p_xch, (size_t)NTOK*HD);

    // s1: fusedW conversions
    launch_convh_s(s1, bgw, p_fWh,                        (size_t)ID*HD);
    launch_convh_s(s1, buw, p_fWh + (size_t)ID*HD,        (size_t)ID*HD);
    launch_convh_s(s1, gA,  p_fWh + (size_t)2*ID*HD,      (size_t)EC*HD);
    launch_convh_s(s1, uA,  p_fWh + (size_t)(2*ID+EC)*HD, (size_t)EC*HD);
    cudaEventRecord(evS1, s1);

    // s2: mid/down operand prep (hidden under x-GEMM)
    launch_convh_s(s2, gB, p_gBh, (size_t)NE*ID*NR);
    launch_convh_s(s2, uB, p_uBh, (size_t)NE*ID*NR);
    launch_convh_s(s2, dA, p_dach, (size_t)EC*ID);
    bcomb_kernel<<<((size_t)HD*KDOWN)/256, 256, 0, s2>>>(bdw, dB);
    cudaEventRecord(evS2, s2);

    // x-side fused GEMM: fp32 baseout + fp16 tg/tu side copy
    cudaStreamWaitEvent(s0, evS1, 0);
    launch_gemm_s(s0, p_xch, p_fWh, p_baseout, NTOK, NF, HD, HD, HD,
                  p_tguh, 2*ID, 2*EC);

    // gateup
    cudaStreamWaitEvent(s0, evS2, 0);
    gateup_kernel<<<dim3(ID/128, MAXTILE), 256, GU_SMEM_BYTES, s0>>>();
    cudaEventRecord(evGate, s0);

    // addhead on s1 concurrent with corr on s0
    cudaStreamWaitEvent(s1, evGate, 0);
    addhead_kernel<<<(NTOK*ID/8)/256, 256, 0, s1>>>();
    cudaEventRecord(evAdd, s1);

    corr_kernel<<<dim3(4, MAXTILE), 128, C_SMEM_BYTES, s0>>>();
    cvec_kernel<<<(NTOK*EC)/256, 256, 0, s0>>>();

    // down projection joins addhead
    cudaStreamWaitEvent(s0, evAdd, 0);
    launch_gemm_s(s0, p_hmixh, p_bcombh, out, NTOK, HD, KDOWN, KDOWN, KDOWN,
                  (__half*)0, 0, 0);
}

// round 17
// speedup vs baseline: 1.9333x; 1.0449x over previous
#include <cuda_runtime.h>
#include <cuda_fp16.h>
#include <cstdint>
#include <math.h>

#define NTOK 2048
#define HD   2048
#define ID   7168
#define NE   8
#define NR   64
#define EC   (NE*NR)       // 512
#define KDOWN (ID+EC)      // 7680
#define NF   (2*ID+2*EC)   // 15360
#define SCALE 0.25f
#define NSLOT (2*NTOK)     // 4096
#define MAXTILE 40

// fp16 GEMM: 128x128x64(halves), 3 stages, 128 threads (4 warps, 2x2 of 64x64)
#define BM 128
#define BN 128
#define STAGES 3
#define STAGE_U32 8192
#define STAGE_BYTES 32768
#define SMEM_BYTES (STAGES*STAGE_BYTES)

// gateup: 4 matrices x (128 x 64 halves) = 64KB
#define GU_SMEM_BYTES 65536

// corr: 128x64x64(halves), 3 stages
#define CK 1792
#define C_STAGE_U32 6144
#define C_STAGE_BYTES 24576
#define C_SMEM_BYTES (3*C_STAGE_BYTES)

// ---------------- scratch ----------------
__device__ __half g_xch   [(size_t)NTOK*HD];
__device__ __half g_fWh   [(size_t)NF*HD];
__device__ __half g_bouth [(size_t)NTOK*NF];      // fp16 (basegate|baseup|tg|tu)
__device__ __half g_hsh   [(size_t)NSLOT*ID];
__device__ __half g_hmixh [(size_t)NTOK*KDOWN];
__device__ float  g_corrp [(size_t)4*NSLOT*NR];
__device__ __half g_bcombh[(size_t)HD*KDOWN];
__device__ __half g_dach  [(size_t)EC*ID];
__device__ __half g_gBh   [(size_t)NE*ID*NR];
__device__ __half g_uBh   [(size_t)NE*ID*NR];
__device__ int    g_eids  [NSLOT];
__device__ float  g_wts   [NSLOT];
__device__ int    g_cnt   [NE];
__device__ int    g_list  [NE*NSLOT];
__device__ int    g_tile_e[MAXTILE+8];
__device__ int    g_tile_base[MAXTILE+8];
__device__ int    g_ntiles;

// ---------------- helpers ----------------
__device__ __forceinline__ void mma_f16(float* c, const uint32_t* a, const uint32_t* b){
    asm volatile(
        "mma.sync.aligned.m16n8k16.row.col.f32.f16.f16.f32 "
        "{%0,%1,%2,%3}, {%4,%5,%6,%7}, {%8,%9}, {%0,%1,%2,%3};"
        : "+f"(c[0]), "+f"(c[1]), "+f"(c[2]), "+f"(c[3])
        : "r"(a[0]), "r"(a[1]), "r"(a[2]), "r"(a[3]), "r"(b[0]), "r"(b[1]));
}
__device__ __forceinline__ void cp16(uint32_t smaddr, const void* g){
    asm volatile("cp.async.cg.shared.global [%0], [%1], 16;" :: "r"(smaddr), "l"(g));
}
__device__ __forceinline__ void cp16z(uint32_t smaddr, const void* g, uint32_t bytes){
    asm volatile("cp.async.cg.shared.global [%0], [%1], 16, %2;"
                 :: "r"(smaddr), "l"(g), "r"(bytes));
}
__device__ __forceinline__ void cp_commit(){
    asm volatile("cp.async.commit_group;" ::: "memory");
}
template<int N> __device__ __forceinline__ void cp_wait(){
    asm volatile("cp.async.wait_group %0;" :: "n"(N) : "memory");
}

// ---------------- fp16 GEMM: C[M,N] = A[M,K]*B[N,K]^T ----------------
// K, lda, ldb in halves. outf16: C viewed as __half[M][N], else float[M][N].
__global__ __launch_bounds__(128, 2) void gemm_h16(
        const __half* __restrict__ A, const __half* __restrict__ B,
        void* __restrict__ C, int M, int N, int K, int lda, int ldb, int outf16){
    extern __shared__ uint32_t sm[];
    const int tid = threadIdx.x;
    const int wid = tid >> 5, lane = tid & 31;
    const int wm = wid >> 1, wn = wid & 1;
    const int grp = lane >> 2, tig = lane & 3;
    const int m0 = blockIdx.y * BM, n0 = blockIdx.x * BN;
    uint32_t smem_base = (uint32_t)__cvta_generic_to_shared(sm);

    const int rA = tid >> 3;
    const int cc = (tid & 7) << 2;
    const uint32_t ccs = (uint32_t)cc ^ (((uint32_t)(rA & 7)) << 2);
    const int ch = cc << 1;
    const __half* Agp = A + (size_t)(m0 + rA) * lda + ch;
    const __half* Bgp = B + (size_t)(n0 + rA) * ldb + ch;
    const size_t rstepA = (size_t)16 * lda;
    const size_t rstepB = (size_t)16 * ldb;

    uint32_t dstA[8], dstB[8];
    #pragma unroll
    for (int q = 0; q < 8; q++){
        dstA[q] = ((uint32_t)(rA + 16*q) * 32u + ccs) * 4u;
        dstB[q] = 16384u + dstA[q];
    }
    const int nch = K >> 6;

    #pragma unroll
    for (int s = 0; s < STAGES-1; s++){
        if (s < nch){
            uint32_t base = smem_base + (uint32_t)s * STAGE_BYTES;
            const __half* ag = Agp + (s << 6);
            const __half* bg = Bgp + (s << 6);
            #pragma unroll
            for (int q = 0; q < 8; q++) cp16(base + dstA[q], ag + rstepA * q);
            #pragma unroll
            for (int q = 0; q < 8; q++) cp16(base + dstB[q], bg + rstepB * q);
        }
        cp_commit();
    }

    const uint32_t gx = (uint32_t)grp << 2;
    uint32_t aRow[4], bRow[8];
    #pragma unroll
    for (int i = 0; i < 4; i++) aRow[i] = (uint32_t)(wm*64 + i*16 + grp) * 32u;
    #pragma unroll
    for (int j = 0; j < 8; j++) bRow[j] = 4096u + (uint32_t)(wn*64 + j*8 + grp) * 32u;

    float acc[4][8][4];
    #pragma unroll
    for (int i = 0; i < 4; i++)
        #pragma unroll
        for (int j = 0; j < 8; j++)
            #pragma unroll
            for (int q = 0; q < 4; q++) acc[i][j][q] = 0.f;

    for (int c = 0; c < nch; c++){
        cp_wait<STAGES-2>();
        __syncthreads();
        if (c + STAGES-1 < nch){
            const int cn = c + STAGES-1;
            uint32_t base = smem_base + (uint32_t)(cn % STAGES) * STAGE_BYTES;
            const __half* ag = Agp + (cn << 6);
            const __half* bg = Bgp + (cn << 6);
            #pragma unroll
            for (int q = 0; q < 8; q++) cp16(base + dstA[q], ag + rstepA * q);
            #pragma unroll
            for (int q = 0; q < 8; q++) cp16(base + dstB[q], bg + rstepB * q);
        }
        cp_commit();

        const uint32_t* st = sm + (size_t)(c % STAGES) * STAGE_U32;
        #pragma unroll
        for (int kk = 0; kk < 4; kk++){
            const uint32_t k0 = ((uint32_t)(kk*8) + tig) ^ gx;
            const uint32_t k1 = ((uint32_t)(kk*8) + tig + 4u) ^ gx;
            uint32_t af[4][4], bf[8][2];
            #pragma unroll
            for (int i = 0; i < 4; i++){
                af[i][0] = st[aRow[i] + k0];
                af[i][1] = st[aRow[i] + 256u + k0];
                af[i][2] = st[aRow[i] + k1];
                af[i][3] = st[aRow[i] + 256u + k1];
            }
            #pragma unroll
            for (int j = 0; j < 8; j++){
                bf[j][0] = st[bRow[j] + k0];
                bf[j][1] = st[bRow[j] + k1];
            }
            #pragma unroll
            for (int i = 0; i < 4; i++)
                #pragma unroll
                for (int j = 0; j < 8; j++)
                    mma_f16(acc[i][j], af[i], bf[j]);
        }
    }

    #pragma unroll
    for (int i = 0; i < 4; i++){
        int r0 = m0 + wm*64 + i*16 + grp;
        #pragma unroll
        for (int j = 0; j < 8; j++){
            int col = n0 + wn*64 + j*8 + (tig << 1);
            float v0 = acc[i][j][0], v1 = acc[i][j][1];
            float v2 = acc[i][j][2], v3 = acc[i][j][3];
            if (outf16){
                __half* c0 = (__half*)C + (size_t)r0 * N + col;
                __half* c1 = (__half*)C + (size_t)(r0 + 8) * N + col;
                *(__half2*)c0 = __floats2half2_rn(v0, v1);
                *(__half2*)c1 = __floats2half2_rn(v2, v3);
            } else {
                float* c0 = (float*)C + (size_t)r0 * N + col;
                float* c1 = (float*)C + (size_t)(r0 + 8) * N + col;
                *(float2*)c0 = make_float2(v0, v1);
                *(float2*)c1 = make_float2(v2, v3);
            }
        }
    }
}

// ---------------- fp32 -> fp16 conversion (8 elems/thread) ----------------
__global__ void convh_kernel(const float* __restrict__ in, __half* __restrict__ out){
    size_t i8 = ((size_t)blockIdx.x * 256 + threadIdx.x) << 3;
    float4 a = *(const float4*)(in + i8);
    float4 b = *(const float4*)(in + i8 + 4);
    __half2 h0 = __floats2half2_rn(a.x, a.y);
    __half2 h1 = __floats2half2_rn(a.z, a.w);
    __half2 h2 = __floats2half2_rn(b.x, b.y);
    __half2 h3 = __floats2half2_rn(b.z, b.w);
    uint4 o;
    o.x = *(uint32_t*)&h0; o.y = *(uint32_t*)&h1;
    o.z = *(uint32_t*)&h2; o.w = *(uint32_t*)&h3;
    *(uint4*)(out + i8) = o;
}

// ---------------- routing + scatter ----------------
__global__ void zero_cnt_kernel(){ if (threadIdx.x < NE) g_cnt[threadIdx.x] = 0; }

__global__ void routing_kernel(const float* __restrict__ x,
                               const float* __restrict__ cw,
                               const float* __restrict__ cb,
                               const float* __restrict__ wealth){
    int t = blockIdx.x;
    int w = threadIdx.x >> 5, lane = threadIdx.x & 31;
    const float* xr = x + (size_t)t * HD;
    const float* cr = cw + (size_t)w * HD;
    float s = 0.f;
    for (int j = lane; j < HD; j += 32) s += xr[j] * cr[j];
    #pragma unroll
    for (int o = 16; o; o >>= 1) s += __shfl_down_sync(0xffffffffu, s, o);
    __shared__ float bids[NE];
    if (lane == 0){
        float conf = 1.f / (1.f + expf(-(s + cb[w])));
        bids[w] = conf * wealth[w];
    }
    __syncthreads();
    if (threadIdx.x == 0){
        int e0 = 0; float b0 = bids[0];
        for (int e = 1; e < NE; e++) if (bids[e] > b0){ b0 = bids[e]; e0 = e; }
        int e1 = -1; float b1 = -1e30f;
        for (int e = 0; e < NE; e++) if (e != e0 && bids[e] > b1){ b1 = bids[e]; e1 = e; }
        float ed = expf(b1 - b0);
        float inv = 1.f / (1.f + ed);
        g_eids[2*t] = e0; g_eids[2*t+1] = e1;
        g_wts [2*t] = inv; g_wts [2*t+1] = ed * inv;
        int p0 = atomicAdd(&g_cnt[e0], 1); g_list[e0*NSLOT + p0] = 2*t;
        int p1 = atomicAdd(&g_cnt[e1], 1); g_list[e1*NSLOT + p1] = 2*t + 1;
    }
}

__global__ void tilemeta_kernel(){
    if (threadIdx.x == 0){
        int nt = 0;
        for (int e = 0; e < NE; e++){
            int c = g_cnt[e];
            for (int b = 0; b < c; b += 128){
                g_tile_e[nt] = e; g_tile_base[nt] = b; nt++;
            }
        }
        g_ntiles = nt;
    }
}

// ---------------- gateup (fp16): 128 slots x 128 i-cols, K=64 ----------------
__global__ __launch_bounds__(256, 2) void gateup_kernel(){
    int tileid = blockIdx.y;
    if (tileid >= g_ntiles) return;
    const int e = g_tile_e[tileid];
    const int tbase = g_tile_base[tileid];
    const int cnt = g_cnt[e];
    const int i0 = blockIdx.x << 7;
    extern __shared__ uint32_t sm[];
    __shared__ int s_ent[128];
    const int tid = threadIdx.x;
    if (tid < 128){
        int j = tbase + tid;
        s_ent[tid] = (j < cnt) ? g_list[e*NSLOT + j] : -1;
    }
    __syncthreads();
    uint32_t smem_base = (uint32_t)__cvta_generic_to_shared(sm);

    {
        const int rA = tid >> 3;
        const int cc = (tid & 7) << 2;
        const uint32_t ccs = (uint32_t)cc ^ (((uint32_t)(rA & 7)) << 2);
        const int ch = cc << 1;
        #pragma unroll
        for (int q = 0; q < 4; q++){
            const int row = rA + 32*q;
            const int ent = s_ent[row];
            const int t = ent >> 1;
            const uint32_t abytes = (ent >= 0) ? 16u : 0u;
            const __half* asrc = (ent >= 0)
                ? (g_bouth + (size_t)t*NF + 2*ID + e*NR + ch)
                : g_bouth;
            const __half* bsrcg = g_gBh + ((size_t)e*ID + i0 + row)*NR + ch;
            const __half* bsrcu = g_uBh + ((size_t)e*ID + i0 + row)*NR + ch;
            const uint32_t dst = ((uint32_t)row*32u + ccs)*4u;
            cp16z(smem_base + dst,            asrc,        abytes);   // Ag (tg)
            cp16z(smem_base + 16384u + dst,   asrc + EC,   abytes);   // Au (tu)
            cp16 (smem_base + 32768u + dst,   bsrcg);
            cp16 (smem_base + 49152u + dst,   bsrcu);
        }
        cp_commit();
    }
    cp_wait<0>();
    __syncthreads();

    const int wid = tid >> 5, lane = tid & 31;
    const int wm = wid >> 2, wn = wid & 3;
    const int grp = lane >> 2, tig = lane & 3;
    const uint32_t gx = (uint32_t)grp << 2;
    const uint32_t* uAg = sm;
    const uint32_t* uAu = sm + 4096;
    const uint32_t* uBg = sm + 8192;
    const uint32_t* uBu = sm + 12288;

    uint32_t aRow[4], bRow[4];
    #pragma unroll
    for (int i = 0; i < 4; i++) aRow[i] = (uint32_t)(wm*64 + i*16 + grp) * 32u;
    #pragma unroll
    for (int j = 0; j < 4; j++) bRow[j] = (uint32_t)(wn*32 + j*8 + grp) * 32u;

    float accg[4][4][4], accu[4][4][4];
    #pragma unroll
    for (int i = 0; i < 4; i++)
        #pragma unroll
        for (int j = 0; j < 4; j++)
            #pragma unroll
            for (int q = 0; q < 4; q++){ accg[i][j][q]=0.f; accu[i][j][q]=0.f; }

    #pragma unroll
    for (int kk = 0; kk < 4; kk++){
        const uint32_t k0 = ((uint32_t)(kk*8) + tig) ^ gx;
        const uint32_t k1 = ((uint32_t)(kk*8) + tig + 4u) ^ gx;
        uint32_t ag[4][4], au[4][4], bg[4][2], bu[4][2];
        #pragma unroll
        for (int i = 0; i < 4; i++){
            ag[i][0] = uAg[aRow[i] + k0];
            ag[i][1] = uAg[aRow[i] + 256u + k0];
            ag[i][2] = uAg[aRow[i] + k1];
            ag[i][3] = uAg[aRow[i] + 256u + k1];
            au[i][0] = uAu[aRow[i] + k0];
            au[i][1] = uAu[aRow[i] + 256u + k0];
            au[i][2] = uAu[aRow[i] + k1];
            au[i][3] = uAu[aRow[i] + 256u + k1];
        }
        #pragma unroll
        for (int j = 0; j < 4; j++){
            bg[j][0] = uBg[bRow[j] + k0];
            bg[j][1] = uBg[bRow[j] + k1];
            bu[j][0] = uBu[bRow[j] + k0];
            bu[j][1] = uBu[bRow[j] + k1];
        }
        #pragma unroll
        for (int i = 0; i < 4; i++)
            #pragma unroll
            for (int j = 0; j < 4; j++){
                mma_f16(accg[i][j], ag[i], bg[j]);
                mma_f16(accu[i][j], au[i], bu[j]);
            }
    }

    // epilogue: fp16 base add + silu*up + weight, write hs fp16
    #pragma unroll
    for (int i = 0; i < 4; i++){
        #pragma unroll
        for (int half_ = 0; half_ < 2; half_++){
            int r = wm*64 + i*16 + grp + half_*8;
            int ent = s_ent[r];
            if (ent < 0) continue;
            int t = ent >> 1;
            float w = g_wts[ent];
            const __half* brow = g_bouth + (size_t)t*NF;
            __half* hrow = g_hsh + (size_t)ent*ID;
            #pragma unroll
            for (int j = 0; j < 4; j++){
                int col = i0 + wn*32 + j*8 + (tig << 1);
                float2 bg2 = __half22float2(*(const __half2*)(brow + col));
                float2 bu2 = __half22float2(*(const __half2*)(brow + ID + col));
                float cg0 = accg[i][j][half_*2+0], cg1 = accg[i][j][half_*2+1];
                float cu0 = accu[i][j][half_*2+0], cu1 = accu[i][j][half_*2+1];
                float gate0 = bg2.x + SCALE*cg0, gate1 = bg2.y + SCALE*cg1;
                float up0 = bu2.x + SCALE*cu0,  up1 = bu2.y + SCALE*cu1;
                float h0 = gate0 * (1.f/(1.f+__expf(-gate0))) * up0;
                float h1 = gate1 * (1.f/(1.f+__expf(-gate1))) * up1;
                *(__half2*)(hrow + col) = __floats2half2_rn(w*h0, w*h1);
            }
        }
    }
}

// ---------------- grouped corr GEMM (fp16 in, fp32 out) ----------------
__global__ __launch_bounds__(128, 2) void corr_kernel(){
    int tileid = blockIdx.y;
    if (tileid >= g_ntiles) return;
    const int e = g_tile_e[tileid];
    const int tbase = g_tile_base[tileid];
    const int cnt = g_cnt[e];
    const int ks = blockIdx.x;
    extern __shared__ uint32_t sm[];
    __shared__ int s_ent[128];
    const int tid = threadIdx.x;
    if (tid < 128){
        int j = tbase + tid;
        s_ent[tid] = (j < cnt) ? g_list[e*NSLOT + j] : -1;
    }
    __syncthreads();
    uint32_t smem_base = (uint32_t)__cvta_generic_to_shared(sm);

    const int rA = tid >> 3;
    const int cc = (tid & 7) << 2;
    const uint32_t ccs = (uint32_t)cc ^ (((uint32_t)(rA & 7)) << 2);
    const int ch = cc << 1;
    const size_t koff0 = (size_t)ks*CK + ch;

    const __half* Asrc[8]; uint32_t Abytes[8];
    #pragma unroll
    for (int q = 0; q < 8; q++){
        int ent = s_ent[rA + 16*q];
        Asrc[q] = (ent >= 0) ? (g_hsh + (size_t)ent*ID + koff0) : g_hsh;
        Abytes[q] = (ent >= 0) ? 16u : 0u;
    }
    const __half* Bsrc[4];
    #pragma unroll
    for (int q = 0; q < 4; q++)
        Bsrc[q] = g_dach + (size_t)(e*NR + rA + 16*q)*ID + koff0;

    uint32_t dstA[8], dstB[4];
    #pragma unroll
    for (int q = 0; q < 8; q++) dstA[q] = ((uint32_t)(rA + 16*q) * 32u + ccs) * 4u;
    #pragma unroll
    for (int q = 0; q < 4; q++) dstB[q] = 16384u + ((uint32_t)(rA + 16*q) * 32u + ccs) * 4u;

    const int nch = CK >> 6;   // 28

    #pragma unroll
    for (int s = 0; s < 2; s++){
        uint32_t base = smem_base + (uint32_t)s * C_STAGE_BYTES;
        #pragma unroll
        for (int q = 0; q < 8; q++) cp16z(base + dstA[q], Asrc[q] + (s<<6), Abytes[q]);
        #pragma unroll
        for (int q = 0; q < 4; q++) cp16(base + dstB[q], Bsrc[q] + (s<<6));
        cp_commit();
    }

    const int wid = tid >> 5, lane = tid & 31;
    const int wm = wid >> 1, wn = wid & 1;
    const int grp = lane >> 2, tig = lane & 3;
    const uint32_t gx = (uint32_t)grp << 2;
    uint32_t aRow[4], bRow[4];
    #pragma unroll
    for (int i = 0; i < 4; i++) aRow[i] = (uint32_t)(wm*64 + i*16 + grp) * 32u;
    #pragma unroll
    for (int j = 0; j < 4; j++) bRow[j] = 4096u + (uint32_t)(wn*32 + j*8 + grp) * 32u;

    float acc[4][4][4];
    #pragma unroll
    for (int i = 0; i < 4; i++)
        #pragma unroll
        for (int j = 0; j < 4; j++)
            #pragma unroll
            for (int q = 0; q < 4; q++) acc[i][j][q] = 0.f;

    for (int c = 0; c < nch; c++){
        cp_wait<1>();
        __syncthreads();
        if (c + 2 < nch){
            const int cn = c + 2;
            uint32_t base = smem_base + (uint32_t)(cn % 3) * C_STAGE_BYTES;
            #pragma unroll
            for (int q = 0; q < 8; q++) cp16z(base + dstA[q], Asrc[q] + (cn<<6), Abytes[q]);
            #pragma unroll
            for (int q = 0; q < 4; q++) cp16(base + dstB[q], Bsrc[q] + (cn<<6));
        }
        cp_commit();

        const uint32_t* st = sm + (size_t)(c % 3) * C_STAGE_U32;
        #pragma unroll
        for (int kk = 0; kk < 4; kk++){
            const uint32_t k0 = ((uint32_t)(kk*8) + tig) ^ gx;
            const uint32_t k1 = ((uint32_t)(kk*8) + tig + 4u) ^ gx;
            uint32_t af[4][4], bf[4][2];
            #pragma unroll
            for (int i = 0; i < 4; i++){
                af[i][0] = st[aRow[i] + k0];
                af[i][1] = st[aRow[i] + 256u + k0];
                af[i][2] = st[aRow[i] + k1];
                af[i][3] = st[aRow[i] + 256u + k1];
            }
            #pragma unroll
            for (int j = 0; j < 4; j++){
                bf[j][0] = st[bRow[j] + k0];
                bf[j][1] = st[bRow[j] + k1];
            }
            #pragma unroll
            for (int i = 0; i < 4; i++)
                #pragma unroll
                for (int j = 0; j < 4; j++)
                    mma_f16(acc[i][j], af[i], bf[j]);
        }
    }

    #pragma unroll
    for (int i = 0; i < 4; i++){
        #pragma unroll
        for (int half_ = 0; half_ < 2; half_++){
            int r = wm*64 + i*16 + grp + half_*8;
            int ent = s_ent[r];
            if (ent < 0) continue;
            float* crow = g_corrp + ((size_t)ks*NSLOT + ent)*NR;
            #pragma unroll
            for (int j = 0; j < 4; j++){
                int col = wn*32 + j*8 + (tig << 1);
                *(float2*)(crow + col) =
                    make_float2(acc[i][j][half_*2+0], acc[i][j][half_*2+1]);
            }
        }
    }
}

// ---------------- bcomb: [bdw | dB repack] -> fp16 ----------------
__global__ void bcomb_kernel(const float* __restrict__ bdw, const float* __restrict__ dB){
    size_t idx = (size_t)blockIdx.x * 256 + threadIdx.x;
    int h = (int)(idx / KDOWN); int k = (int)(idx % KDOWN);
    float v;
    if (k < ID) v = bdw[(size_t)h * ID + k];
    else { int j = k - ID; int e = j >> 6; int r = j & 63;
           v = dB[((size_t)e * HD + h) * NR + r]; }
    g_bcombh[idx] = __float2half_rn(v);
}

// hmix head: hs0+hs1 -> fp16
__global__ void addhead_kernel(){
    size_t i8 = ((size_t)blockIdx.x * 256 + threadIdx.x) << 3;
    int t = (int)(i8 / ID); int col = (int)(i8 % ID);
    const __half2* a = (const __half2*)(g_hsh + (size_t)(2*t)*ID + col);
    const __half2* b = (const __half2*)(g_hsh + (size_t)(2*t+1)*ID + col);
    __half2* o = (__half2*)(g_hmixh + (size_t)t * KDOWN + col);
    #pragma unroll
    for (int q = 0; q < 4; q++){
        float2 fa = __half22float2(a[q]);
        float2 fb = __half22float2(b[q]);
        o[q] = __floats2half2_rn(fa.x + fb.x, fa.y + fb.y);
    }
}

// cvec tail -> fp16
__global__ void cvec_kernel(){
    int idx = blockIdx.x * 256 + threadIdx.x;
    int t = idx >> 9, j = idx & 511;
    int e = j >> 6, r = j & 63;
    float v = 0.f;
    #pragma unroll
    for (int k = 0; k < 2; k++){
        int ent = 2*t + k;
        if (g_eids[ent] == e){
            #pragma unroll
            for (int s = 0; s < 4; s++)
                v += g_corrp[((size_t)s*NSLOT + ent)*NR + r];
        }
    }
    g_hmixh[(size_t)t * KDOWN + ID + j] = __float2half_rn(SCALE * v);
}

// ---------------- launch ----------------
static void launch_gemm_s(cudaStream_t st, const __half* A, const __half* B, void* C,
                          int M, int N, int K, int lda, int ldb, int outf16){
    dim3 grid(N / BN, M / BM);
    gemm_h16<<<grid, 128, SMEM_BYTES, st>>>(A, B, C, M, N, K, lda, ldb, outf16);
}
static void launch_convh_s(cudaStream_t st, const float* in, __half* out, size_t n){
    convh_kernel<<<(unsigned)((n / 8) / 256), 256, 0, st>>>(in, out);
}

extern "C" void kernel_launch(void* const* d_in, const int* in_sizes, int n_in,
                              void* d_out, int out_size){
    const float* x      = (const float*)d_in[0];
    const float* conf_w = (const float*)d_in[1];
    const float* conf_b = (const float*)d_in[2];
    const float* wealth = (const float*)d_in[3];
    const float* bgw    = (const float*)d_in[4];
    const float* buw    = (const float*)d_in[5];
    const float* bdw    = (const float*)d_in[6];
    const float* gA     = (const float*)d_in[7];
    const float* gB     = (const float*)d_in[8];
    const float* uA     = (const float*)d_in[9];
    const float* uB     = (const float*)d_in[10];
    const float* dA     = (const float*)d_in[11];
    const float* dB     = (const float*)d_in[12];
    float* out = (float*)d_out;

    static bool init_done = false;
    static cudaStream_t s1, s2;
    static cudaEvent_t evFork, evS1, evS2, evGate, evAdd;
    if (!init_done){
        cudaFuncSetAttribute(gemm_h16, cudaFuncAttributeMaxDynamicSharedMemorySize, SMEM_BYTES);
        cudaFuncSetAttribute(gateup_kernel, cudaFuncAttributeMaxDynamicSharedMemorySize, GU_SMEM_BYTES);
        cudaFuncSetAttribute(corr_kernel, cudaFuncAttributeMaxDynamicSharedMemorySize, C_SMEM_BYTES);
        cudaStreamCreateWithFlags(&s1, cudaStreamNonBlocking);
        cudaStreamCreateWithFlags(&s2, cudaStreamNonBlocking);
        cudaEventCreateWithFlags(&evFork, cudaEventDisableTiming);
        cudaEventCreateWithFlags(&evS1,   cudaEventDisableTiming);
        cudaEventCreateWithFlags(&evS2,   cudaEventDisableTiming);
        cudaEventCreateWithFlags(&evGate, cudaEventDisableTiming);
        cudaEventCreateWithFlags(&evAdd,  cudaEventDisableTiming);
        init_done = true;
    }

    __half *p_xch, *p_fWh, *p_bouth, *p_hmixh, *p_bcombh, *p_dach, *p_gBh, *p_uBh;
    cudaGetSymbolAddress((void**)&p_xch,     g_xch);
    cudaGetSymbolAddress((void**)&p_fWh,     g_fWh);
    cudaGetSymbolAddress((void**)&p_bouth,   g_bouth);
    cudaGetSymbolAddress((void**)&p_hmixh,   g_hmixh);
    cudaGetSymbolAddress((void**)&p_bcombh,  g_bcombh);
    cudaGetSymbolAddress((void**)&p_dach,    g_dach);
    cudaGetSymbolAddress((void**)&p_gBh,     g_gBh);
    cudaGetSymbolAddress((void**)&p_uBh,     g_uBh);

    cudaStream_t s0 = 0;

    cudaEventRecord(evFork, s0);
    cudaStreamWaitEvent(s1, evFork, 0);
    cudaStreamWaitEvent(s2, evFork, 0);

    // s0: routing path + x conversion
    zero_cnt_kernel<<<1, 32, 0, s0>>>();
    routing_kernel<<<NTOK, 256, 0, s0>>>(x, conf_w, conf_b, wealth);
    tilemeta_kernel<<<1, 32, 0, s0>>>();
    launch_convh_s(s0, x, p_xch, (size_t)NTOK*HD);

    // s1: fusedW conversions
    launch_convh_s(s1, bgw, p_fWh,                        (size_t)ID*HD);
    launch_convh_s(s1, buw, p_fWh + (size_t)ID*HD,        (size_t)ID*HD);
    launch_convh_s(s1, gA,  p_fWh + (size_t)2*ID*HD,      (size_t)EC*HD);
    launch_convh_s(s1, uA,  p_fWh + (size_t)(2*ID+EC)*HD, (size_t)EC*HD);
    cudaEventRecord(evS1, s1);

    // s2: mid/down operand prep (hidden under x-GEMM)
    launch_convh_s(s2, gB, p_gBh, (size_t)NE*ID*NR);
    launch_convh_s(s2, uB, p_uBh, (size_t)NE*ID*NR);
    launch_convh_s(s2, dA, p_dach, (size_t)EC*ID);
    bcomb_kernel<<<((size_t)HD*KDOWN)/256, 256, 0, s2>>>(bdw, dB);
    cudaEventRecord(evS2, s2);

    // x-side fused GEMM -> fp16 bouth
    cudaStreamWaitEvent(s0, evS1, 0);
    launch_gemm_s(s0, p_xch, p_fWh, p_bouth, NTOK, NF, HD, HD, HD, 1);

    // gateup
    cudaStreamWaitEvent(s0, evS2, 0);
    gateup_kernel<<<dim3(ID/128, MAXTILE), 256, GU_SMEM_BYTES, s0>>>();
    cudaEventRecord(evGate, s0);

    // addhead on s1 concurrent with corr on s0
    cudaStreamWaitEvent(s1, evGate, 0);
    addhead_kernel<<<(NTOK*ID/8)/256, 256, 0, s1>>>();
    cudaEventRecord(evAdd, s1);

    corr_kernel<<<dim3(4, MAXTILE), 128, C_SMEM_BYTES, s0>>>();
    cvec_kernel<<<(NTOK*EC)/256, 256, 0, s0>>>();

    // down projection joins addhead (fp32 out)
    cudaStreamWaitEvent(s0, evAdd, 0);
    launch_gemm_s(s0, p_hmixh, p_bcombh, out, NTOK, HD, KDOWN, KDOWN, KDOWN, 0);
}